// round 8
// baseline (speedup 1.0000x reference)
#include <cuda_runtime.h>
#include <cuda_bf16.h>
#include <math.h>

// Problem constants
#define BB   64      // batch
#define TT   256     // time
#define HH   1024    // hidden
#define G3   3072    // 3*H
#define VV   128     // vocab

// Scratch (device globals: sanctioned allocation-free workaround)
__device__ float g_y0f[(size_t)BB * TT * HH];            // layer0 forward outputs  [b][t][h]
__device__ float g_y0b[(size_t)BB * TT * HH];            // layer0 backward outputs [b][t][h]
__device__ float g_xp1[(size_t)2 * TT * BB * G3];        // layer1 input projections [dir][t][b][3H]

// ---------------------------------------------------------------------------
// GRU recurrent step. One launch per timestep s, grid (64, 2):
//   blockIdx.y = direction, blockIdx.x -> (batch half, 32-col gate group).
// Each CTA: 32 batches x 32 gate-cols x 3 gate strips, K=1024, fused epilogue.
// ---------------------------------------------------------------------------
template <int LAYER>
__global__ __launch_bounds__(256, 1)
void gru_step_kernel(const float* __restrict__ Whh,   // [2][3072][1024]
                     const float* __restrict__ bhh,   // [2][3072]
                     const float* __restrict__ Wih0,  // [2][3072][128]  (layer 0 only)
                     const float* __restrict__ bih0,  // [2][3072]      (layer 0 only)
                     const int*   __restrict__ xtok,  // [64][256]
                     float* __restrict__ dout,        // layer1 output base (d_out)
                     int s)
{
    const int dir = blockIdx.y;
    const int b0  = (blockIdx.x & 1) * 32;
    const int j0  = (blockIdx.x >> 1) * 32;
    const int tx  = threadIdx.x & 31;
    const int ty  = threadIdx.x >> 5;   // 0..7 (warp id)
    const int ty4 = ty * 4;

    const int t_x   = dir ? (TT - 1 - s) : s;
    const int tprev = dir ? (t_x + 1) : (t_x - 1);

    float* yF;
    float* yB;
    int tStride, bStride;
    if (LAYER == 0) { yF = g_y0f; yB = g_y0b; tStride = HH;    bStride = TT * HH;    }
    else            { yF = dout;  yB = dout + HH; tStride = 2*HH; bStride = TT * 2*HH; }
    float* Y = dir ? yB : yF;

    const float* Wd   = Whh + (size_t)dir * G3 * HH;
    const float* bhhd = bhh + dir * G3;

    __shared__ float hs[32][36];        // hs[k][b]   (padded, float4-aligned reads)
    __shared__ float ws[3][32][33];     // ws[g][j][k] (conflict-free k reads)

    const int q  = threadIdx.x;
    const int rb = q >> 3;              // 0..31 (row for staging: batch / gate-col)
    const int kq = (q & 7) * 4;         // 0..28 (k quad)

    float acc[3][4];
#pragma unroll
    for (int g = 0; g < 3; ++g)
#pragma unroll
        for (int i = 0; i < 4; ++i) acc[g][i] = 0.f;

    float4 hv, wv0, wv1, wv2;
    // prefetch stage 0
    {
        if (s > 0)
            hv = *(const float4*)&Y[(size_t)(b0 + rb) * bStride + (size_t)tprev * tStride + kq];
        else
            hv = make_float4(0.f, 0.f, 0.f, 0.f);
        wv0 = *(const float4*)&Wd[(size_t)(0 * HH + j0 + rb) * HH + kq];
        wv1 = *(const float4*)&Wd[(size_t)(1 * HH + j0 + rb) * HH + kq];
        wv2 = *(const float4*)&Wd[(size_t)(2 * HH + j0 + rb) * HH + kq];
    }

    for (int st = 0; st < 32; ++st) {
        // store prefetched stage
        hs[kq + 0][rb] = hv.x; hs[kq + 1][rb] = hv.y;
        hs[kq + 2][rb] = hv.z; hs[kq + 3][rb] = hv.w;
        ws[0][rb][kq + 0] = wv0.x; ws[0][rb][kq + 1] = wv0.y;
        ws[0][rb][kq + 2] = wv0.z; ws[0][rb][kq + 3] = wv0.w;
        ws[1][rb][kq + 0] = wv1.x; ws[1][rb][kq + 1] = wv1.y;
        ws[1][rb][kq + 2] = wv1.z; ws[1][rb][kq + 3] = wv1.w;
        ws[2][rb][kq + 0] = wv2.x; ws[2][rb][kq + 1] = wv2.y;
        ws[2][rb][kq + 2] = wv2.z; ws[2][rb][kq + 3] = wv2.w;
        __syncthreads();

        // prefetch next stage (overlaps with compute)
        if (st + 1 < 32) {
            const int k0 = (st + 1) * 32;
            if (s > 0)
                hv = *(const float4*)&Y[(size_t)(b0 + rb) * bStride + (size_t)tprev * tStride + k0 + kq];
            else
                hv = make_float4(0.f, 0.f, 0.f, 0.f);
            wv0 = *(const float4*)&Wd[(size_t)(0 * HH + j0 + rb) * HH + k0 + kq];
            wv1 = *(const float4*)&Wd[(size_t)(1 * HH + j0 + rb) * HH + k0 + kq];
            wv2 = *(const float4*)&Wd[(size_t)(2 * HH + j0 + rb) * HH + k0 + kq];
        }

#pragma unroll
        for (int k = 0; k < 32; ++k) {
            float4 a = *(const float4*)&hs[k][ty4];   // broadcast across warp
            float w0 = ws[0][tx][k];
            float w1 = ws[1][tx][k];
            float w2 = ws[2][tx][k];
            acc[0][0] += a.x * w0; acc[0][1] += a.y * w0;
            acc[0][2] += a.z * w0; acc[0][3] += a.w * w0;
            acc[1][0] += a.x * w1; acc[1][1] += a.y * w1;
            acc[1][2] += a.z * w1; acc[1][3] += a.w * w1;
            acc[2][0] += a.x * w2; acc[2][1] += a.y * w2;
            acc[2][2] += a.z * w2; acc[2][3] += a.w * w2;
        }
        __syncthreads();
    }

    // ---------------- fused gate epilogue ----------------
    const int j = j0 + tx;
    const float bhr = bhhd[j];
    const float bhz = bhhd[HH + j];
    const float bhn = bhhd[2 * HH + j];

    const float* Wih0d = 0;
    float bir = 0.f, biz = 0.f, bin_ = 0.f;
    if (LAYER == 0) {
        Wih0d = Wih0 + (size_t)dir * G3 * VV;
        const float* bih0d = bih0 + dir * G3;
        bir  = bih0d[j];
        biz  = bih0d[HH + j];
        bin_ = bih0d[2 * HH + j];
    }

#pragma unroll
    for (int i = 0; i < 4; ++i) {
        const int b = b0 + ty4 + i;
        float gr = acc[0][i] + bhr;
        float gz = acc[1][i] + bhz;
        float gn = acc[2][i] + bhn;
        float xr, xz, xn;
        if (LAYER == 0) {
            const int tok = xtok[b * TT + t_x];
            xr = Wih0d[(size_t)j * VV + tok] + bir;
            xz = Wih0d[(size_t)(HH + j) * VV + tok] + biz;
            xn = Wih0d[(size_t)(2 * HH + j) * VV + tok] + bin_;
        } else {
            const float* xp = g_xp1 + (((size_t)dir * TT + t_x) * BB + b) * G3;
            xr = xp[j];
            xz = xp[HH + j];
            xn = xp[2 * HH + j];
        }
        float r = 1.f / (1.f + expf(-(xr + gr)));
        float z = 1.f / (1.f + expf(-(xz + gz)));
        float n = tanhf(xn + r * gn);
        float hp = 0.f;
        if (s > 0) hp = Y[(size_t)b * bStride + (size_t)tprev * tStride + j];
        Y[(size_t)b * bStride + (size_t)t_x * tStride + j] = (1.f - z) * n + z * hp;
    }
}

// ---------------------------------------------------------------------------
// Layer-1 input projection:
//   xp1[dir][t][b][g] = sum_k y0cat[b][t][k] * Wih1[dir][g][k] + bih1[dir][g]
//   y0cat = [g_y0f | g_y0b] along k (2048).
// 64x64 tile, 4x4 micro, K-tile 16, register prefetch.
// ---------------------------------------------------------------------------
__global__ __launch_bounds__(256)
void xp1_gemm_kernel(const float* __restrict__ Wih1,   // [2][3072][2048]
                     const float* __restrict__ bih1)   // [2][3072]
{
    const int dir = blockIdx.z;
    const float* W  = Wih1 + (size_t)dir * G3 * (2 * HH);
    const float* bi = bih1 + dir * G3;
    const int i0 = blockIdx.x * 64;   // row tile over (b,t) = i, i = b*256 + t
    const int j0 = blockIdx.y * 64;   // col tile over g

    __shared__ float As[16][68];
    __shared__ float Bs[16][68];

    const int tid = threadIdx.x;
    const int ti  = tid & 15;
    const int tj  = tid >> 4;
    const int ra  = tid >> 2;          // 0..63 staging row
    const int kq  = (tid & 3) * 4;     // 0..12 staging k quad

    float acc[4][4];
#pragma unroll
    for (int m = 0; m < 4; ++m)
#pragma unroll
        for (int n = 0; n < 4; ++n) acc[m][n] = 0.f;

    // prefetch stage 0
    float4 av, bv;
    {
        const int k = kq;
        const float* src = (k < HH) ? (g_y0f + (size_t)(i0 + ra) * HH + k)
                                    : (g_y0b + (size_t)(i0 + ra) * HH + (k - HH));
        av = *(const float4*)src;
        bv = *(const float4*)&W[(size_t)(j0 + ra) * (2 * HH) + k];
    }

    for (int kt = 0; kt < 2 * HH; kt += 16) {
        As[kq + 0][ra] = av.x; As[kq + 1][ra] = av.y;
        As[kq + 2][ra] = av.z; As[kq + 3][ra] = av.w;
        Bs[kq + 0][ra] = bv.x; Bs[kq + 1][ra] = bv.y;
        Bs[kq + 2][ra] = bv.z; Bs[kq + 3][ra] = bv.w;
        __syncthreads();

        if (kt + 16 < 2 * HH) {
            const int k = kt + 16 + kq;
            const float* src = (k < HH) ? (g_y0f + (size_t)(i0 + ra) * HH + k)
                                        : (g_y0b + (size_t)(i0 + ra) * HH + (k - HH));
            av = *(const float4*)src;
            bv = *(const float4*)&W[(size_t)(j0 + ra) * (2 * HH) + k];
        }

#pragma unroll
        for (int k = 0; k < 16; ++k) {
            float4 a = *(const float4*)&As[k][ti * 4];
            float4 b = *(const float4*)&Bs[k][tj * 4];
            acc[0][0] += a.x * b.x; acc[0][1] += a.x * b.y; acc[0][2] += a.x * b.z; acc[0][3] += a.x * b.w;
            acc[1][0] += a.y * b.x; acc[1][1] += a.y * b.y; acc[1][2] += a.y * b.z; acc[1][3] += a.y * b.w;
            acc[2][0] += a.z * b.x; acc[2][1] += a.z * b.y; acc[2][2] += a.z * b.z; acc[2][3] += a.z * b.w;
            acc[3][0] += a.w * b.x; acc[3][1] += a.w * b.y; acc[3][2] += a.w * b.z; acc[3][3] += a.w * b.w;
        }
        __syncthreads();
    }

    // epilogue: + bih1, scatter to xp1[dir][t][b][g]
    const int jb = j0 + tj * 4;
    const float b0v = bi[jb + 0], b1v = bi[jb + 1], b2v = bi[jb + 2], b3v = bi[jb + 3];
#pragma unroll
    for (int m = 0; m < 4; ++m) {
        const int i = i0 + ti * 4 + m;
        const int b = i >> 8;     // /256
        const int t = i & 255;
        float4 o;
        o.x = acc[m][0] + b0v;
        o.y = acc[m][1] + b1v;
        o.z = acc[m][2] + b2v;
        o.w = acc[m][3] + b3v;
        float* dst = g_xp1 + (((size_t)dir * TT + t) * BB + b) * G3 + jb;
        *(float4*)dst = o;
    }
}

// ---------------------------------------------------------------------------
// Final hidden-state stack: out[BTH2 + l*B*H + b*H + h], l in {hf0, hb0, hf1, hb1}
// ---------------------------------------------------------------------------
__global__ void finalize_kernel(float* __restrict__ dout)
{
    const int idx = blockIdx.x * blockDim.x + threadIdx.x;   // < 4*64*1024
    const int l = idx >> 16;
    const int r = idx & 65535;
    const int b = r >> 10;
    const int h = r & 1023;
    float v;
    if (l == 0)      v = g_y0f[((size_t)b * TT + (TT - 1)) * HH + h];
    else if (l == 1) v = g_y0b[((size_t)b * TT + 0) * HH + h];
    else if (l == 2) v = dout[((size_t)b * TT + (TT - 1)) * (2 * HH) + h];
    else             v = dout[((size_t)b * TT + 0) * (2 * HH) + HH + h];
    dout[(size_t)BB * TT * 2 * HH + idx] = v;
}

// ---------------------------------------------------------------------------
extern "C" void kernel_launch(void* const* d_in, const int* in_sizes, int n_in,
                              void* d_out, int out_size)
{
    (void)in_sizes; (void)n_in; (void)out_size;
    const int*   x    = (const int*)  d_in[0];
    const float* Wih0 = (const float*)d_in[1];
    const float* Whh0 = (const float*)d_in[2];
    const float* bih0 = (const float*)d_in[3];
    const float* bhh0 = (const float*)d_in[4];
    const float* Wih1 = (const float*)d_in[5];
    const float* Whh1 = (const float*)d_in[6];
    const float* bih1 = (const float*)d_in[7];
    const float* bhh1 = (const float*)d_in[8];
    float* out = (float*)d_out;

    dim3 sgrid(64, 2, 1);

    // Layer 0: both directions per step, 256 steps
    for (int s = 0; s < TT; ++s)
        gru_step_kernel<0><<<sgrid, 256>>>(Whh0, bhh0, Wih0, bih0, x, out, s);

    // Layer 1 input projections (bulk GEMM over full sequence, both dirs)
    xp1_gemm_kernel<<<dim3(256, 48, 2), 256>>>(Wih1, bih1);

    // Layer 1: both directions per step, writes straight into d_out
    for (int s = 0; s < TT; ++s)
        gru_step_kernel<1><<<sgrid, 256>>>(Whh1, bhh1, (const float*)0, (const float*)0, x, out, s);

    // Hidden-state stack
    finalize_kernel<<<1024, 256>>>(out);
}

// round 10
// speedup vs baseline: 1.9299x; 1.9299x over previous
#include <cuda_runtime.h>
#include <cuda_bf16.h>
#include <math.h>
#include <stdint.h>

// Problem constants
#define BB   64      // batch
#define TT   256     // time
#define HH   1024    // hidden
#define G3   3072    // 3*H
#define VV   128     // vocab

// ---------------------------------------------------------------------------
// Device-global scratch (allocation-free workaround)
// ---------------------------------------------------------------------------
__device__ __align__(16) float g_y0f[(size_t)BB * TT * HH];     // layer0 fwd y [b][t][h]
__device__ __align__(16) float g_y0b[(size_t)BB * TT * HH];     // layer0 bwd y [b][t][h]
__device__ __align__(16) float g_xp1[(size_t)2 * TT * BB * G3]; // layer1 x-proj [dir][t][b][3H]
__device__ __align__(16) __nv_bfloat16 g_yhi[(size_t)BB * TT * 2 * HH]; // y0cat hi [i][2048]
__device__ __align__(16) __nv_bfloat16 g_ylo[(size_t)BB * TT * 2 * HH]; // y0cat lo
__device__ __align__(16) __nv_bfloat16 g_whi[(size_t)2 * G3 * 2 * HH];  // Wih1 hi [dir][3072][2048]
__device__ __align__(16) __nv_bfloat16 g_wlo[(size_t)2 * G3 * 2 * HH];  // Wih1 lo
__device__ __align__(16) __nv_bfloat16 g_whh_hi[(size_t)2 * 2 * G3 * HH]; // Whh hi [layer][dir][3072][1024]
__device__ __align__(16) __nv_bfloat16 g_whh_lo[(size_t)2 * 2 * G3 * HH]; // Whh lo
__device__ __align__(16) __nv_bfloat16 g_hhi[(size_t)2 * 2 * BB * HH];  // h state hi [dir][parity][64][1024]
__device__ __align__(16) __nv_bfloat16 g_hlo[(size_t)2 * 2 * BB * HH];  // h state lo

// ---------------------------------------------------------------------------
// mma.sync m16n8k16 bf16 -> f32 (standard PTX, works on base sm_103 target)
// A row-major fragment a0..a3, B col-major fragment b0..b1, C/D 4x f32.
// ---------------------------------------------------------------------------
__device__ __forceinline__ void mma_bf16(float d[4],
                                         uint32_t a0, uint32_t a1, uint32_t a2, uint32_t a3,
                                         uint32_t b0, uint32_t b1)
{
    asm volatile(
        "mma.sync.aligned.m16n8k16.row.col.f32.bf16.bf16.f32 "
        "{%0,%1,%2,%3}, {%4,%5,%6,%7}, {%8,%9}, {%0,%1,%2,%3};\n"
        : "+f"(d[0]), "+f"(d[1]), "+f"(d[2]), "+f"(d[3])
        : "r"(a0), "r"(a1), "r"(a2), "r"(a3), "r"(b0), "r"(b1));
}

// ---------------------------------------------------------------------------
// Split kernels (fp32 -> hi/lo bf16)
// ---------------------------------------------------------------------------
__global__ void split_whh_kernel(const float* __restrict__ Whh0,
                                 const float* __restrict__ Whh1)
{
    const size_t idx = (size_t)blockIdx.x * 256 + threadIdx.x;
    const size_t per_layer = (size_t)2 * G3 * HH;
    if (idx >= 2 * per_layer) return;
    float w = (idx < per_layer) ? Whh0[idx] : Whh1[idx - per_layer];
    __nv_bfloat16 h = __float2bfloat16(w);
    g_whh_hi[idx] = h;
    g_whh_lo[idx] = __float2bfloat16(w - __bfloat162float(h));
}

__global__ void split_wih1_kernel(const float* __restrict__ Wih1)
{
    const size_t idx = (size_t)blockIdx.x * 256 + threadIdx.x;
    if (idx >= (size_t)2 * G3 * 2 * HH) return;
    float w = Wih1[idx];
    __nv_bfloat16 h = __float2bfloat16(w);
    g_whi[idx] = h;
    g_wlo[idx] = __float2bfloat16(w - __bfloat162float(h));
}

__global__ void split_y_kernel()
{
    const size_t idx = (size_t)blockIdx.x * 256 + threadIdx.x;
    if (idx >= (size_t)BB * TT * 2 * HH) return;
    const size_t i = idx >> 11;        // row (b*256+t)
    const int    k = (int)(idx & 2047);
    float v = (k < HH) ? g_y0f[i * HH + k] : g_y0b[i * HH + (k - HH)];
    __nv_bfloat16 h = __float2bfloat16(v);
    g_yhi[idx] = h;
    g_ylo[idx] = __float2bfloat16(v - __bfloat162float(h));
}

// ---------------------------------------------------------------------------
// GRU recurrent step on tensor cores (bf16x3 split, fp32 accum).
// One launch per timestep s. grid (64, 2): x = j-tile (16 cols), y = dir.
// block = 384 (12 warps): warp = (m-tile 0..3) x (gate 0..2), 16x16 output.
// K = 1024, chunk 32, double-buffered smem, fused gate epilogue.
// ---------------------------------------------------------------------------
#define SA_STRIDE 40
#define STEP_SA_BYTES (2 * 2 * 64 * SA_STRIDE * 2)   // 20480
#define STEP_SB_BYTES (2 * 2 * 48 * SA_STRIDE * 2)   // 15360

template <int LAYER>
__global__ __launch_bounds__(384, 1)
void gru_step_mma(const float* __restrict__ bhh,    // [2][3072] (this layer)
                  const float* __restrict__ Wih0,   // [2][3072][128] (layer 0 only)
                  const float* __restrict__ bih0,   // [2][3072]     (layer 0 only)
                  const int*   __restrict__ xtok,   // [64][256]
                  float* __restrict__ dout,
                  int s)
{
    __shared__ __align__(16) char smem[STEP_SA_BYTES + STEP_SB_BYTES]; // 35840
    __nv_bfloat16* sA = (__nv_bfloat16*)smem;                    // [buf][hl][64][40]
    __nv_bfloat16* sB = (__nv_bfloat16*)(smem + STEP_SA_BYTES);  // [buf][hl][48][40]
    float*         sG = (float*)smem;                            // [3][64][20] (aliased)

    const int dir = blockIdx.y;
    const int j0  = blockIdx.x * 16;
    const int tid = threadIdx.x;
    const int wid = tid >> 5;
    const int lid = tid & 31;
    const int gid = lid >> 2;
    const int tg2 = (lid & 3) * 2;
    const int mt  = wid & 3;      // m-tile (batches mt*16..+15)
    const int gg  = wid >> 2;     // gate 0..2

    const int t_x   = dir ? (TT - 1 - s) : s;
    const int tprev = dir ? (t_x + 1) : (t_x - 1);
    const int par   = s & 1;
    const int parN  = (s + 1) & 1;

    float* yF; float* yB;
    int tStride, bStride;
    if (LAYER == 0) { yF = g_y0f; yB = g_y0b;  tStride = HH;     bStride = TT * HH;     }
    else            { yF = dout;  yB = dout + HH; tStride = 2*HH; bStride = TT * 2*HH; }
    float* Y = dir ? yB : yF;

    const __nv_bfloat16* Ahi = g_hhi + ((size_t)(dir * 2 + par)) * BB * HH;
    const __nv_bfloat16* Alo = g_hlo + ((size_t)(dir * 2 + par)) * BB * HH;
    const __nv_bfloat16* Bhi = g_whh_hi + ((size_t)(LAYER * 2 + dir)) * G3 * HH;
    const __nv_bfloat16* Blo = g_whh_lo + ((size_t)(LAYER * 2 + dir)) * G3 * HH;

    float acc[2][4];
#pragma unroll
    for (int nf = 0; nf < 2; ++nf)
#pragma unroll
        for (int q = 0; q < 4; ++q) acc[nf][q] = 0.f;

    if (s > 0) {
        // staging roles
        const int arow  = tid >> 2;          // 0..95 (valid if tid<256 -> 0..63)
        const int apart = tid & 3;
        const bool doA  = (tid < 256);
        const bool doB  = (tid < 192);
        int wrow = 0;
        if (doB) {
            const int brow = tid >> 2;       // 0..47
            wrow = (brow >> 4) * HH + j0 + (brow & 15);
        }

        uint4 pah, pal, pbh, pbl;
        if (doA) {
            pah = *(const uint4*)(Ahi + (size_t)arow * HH + apart * 8);
            pal = *(const uint4*)(Alo + (size_t)arow * HH + apart * 8);
        }
        if (doB) {
            pbh = *(const uint4*)(Bhi + (size_t)wrow * HH + apart * 8);
            pbl = *(const uint4*)(Blo + (size_t)wrow * HH + apart * 8);
        }

        for (int st = 0; st < 32; ++st) {
            const int p = st & 1;
            if (doA) {
                *(uint4*)(sA + ((p * 2 + 0) * 64 + arow) * SA_STRIDE + apart * 8) = pah;
                *(uint4*)(sA + ((p * 2 + 1) * 64 + arow) * SA_STRIDE + apart * 8) = pal;
            }
            if (doB) {
                const int brow = tid >> 2;
                *(uint4*)(sB + ((p * 2 + 0) * 48 + brow) * SA_STRIDE + apart * 8) = pbh;
                *(uint4*)(sB + ((p * 2 + 1) * 48 + brow) * SA_STRIDE + apart * 8) = pbl;
            }
            __syncthreads();

            if (st + 1 < 32) {
                const int kc = (st + 1) * 32;
                if (doA) {
                    pah = *(const uint4*)(Ahi + (size_t)arow * HH + kc + apart * 8);
                    pal = *(const uint4*)(Alo + (size_t)arow * HH + kc + apart * 8);
                }
                if (doB) {
                    pbh = *(const uint4*)(Bhi + (size_t)wrow * HH + kc + apart * 8);
                    pbl = *(const uint4*)(Blo + (size_t)wrow * HH + kc + apart * 8);
                }
            }

            const int ar = mt * 16 + gid;
#pragma unroll
            for (int kk = 0; kk < 32; kk += 16) {
                uint32_t ah0 = *(const uint32_t*)(sA + ((p*2+0)*64 + ar    ) * SA_STRIDE + kk + tg2);
                uint32_t ah1 = *(const uint32_t*)(sA + ((p*2+0)*64 + ar + 8) * SA_STRIDE + kk + tg2);
                uint32_t ah2 = *(const uint32_t*)(sA + ((p*2+0)*64 + ar    ) * SA_STRIDE + kk + tg2 + 8);
                uint32_t ah3 = *(const uint32_t*)(sA + ((p*2+0)*64 + ar + 8) * SA_STRIDE + kk + tg2 + 8);
                uint32_t al0 = *(const uint32_t*)(sA + ((p*2+1)*64 + ar    ) * SA_STRIDE + kk + tg2);
                uint32_t al1 = *(const uint32_t*)(sA + ((p*2+1)*64 + ar + 8) * SA_STRIDE + kk + tg2);
                uint32_t al2 = *(const uint32_t*)(sA + ((p*2+1)*64 + ar    ) * SA_STRIDE + kk + tg2 + 8);
                uint32_t al3 = *(const uint32_t*)(sA + ((p*2+1)*64 + ar + 8) * SA_STRIDE + kk + tg2 + 8);
#pragma unroll
                for (int nf = 0; nf < 2; ++nf) {
                    const int br = gg * 16 + nf * 8 + gid;
                    uint32_t bh0 = *(const uint32_t*)(sB + ((p*2+0)*48 + br) * SA_STRIDE + kk + tg2);
                    uint32_t bh1 = *(const uint32_t*)(sB + ((p*2+0)*48 + br) * SA_STRIDE + kk + tg2 + 8);
                    uint32_t bl0 = *(const uint32_t*)(sB + ((p*2+1)*48 + br) * SA_STRIDE + kk + tg2);
                    uint32_t bl1 = *(const uint32_t*)(sB + ((p*2+1)*48 + br) * SA_STRIDE + kk + tg2 + 8);
                    mma_bf16(acc[nf], ah0, ah1, ah2, ah3, bh0, bh1);
                    mma_bf16(acc[nf], al0, al1, al2, al3, bh0, bh1);
                    mma_bf16(acc[nf], ah0, ah1, ah2, ah3, bl0, bl1);
                }
            }
        }

        __syncthreads();  // all reads of sA/sB done before aliasing as sG

        // exchange gate blocks through smem: sG[g][b][jl] (pad 20)
        const int r0 = mt * 16 + gid;
#pragma unroll
        for (int nf = 0; nf < 2; ++nf) {
            const int c0 = nf * 8 + tg2;
            sG[(gg * 64 + r0    ) * 20 + c0    ] = acc[nf][0];
            sG[(gg * 64 + r0    ) * 20 + c0 + 1] = acc[nf][1];
            sG[(gg * 64 + r0 + 8) * 20 + c0    ] = acc[nf][2];
            sG[(gg * 64 + r0 + 8) * 20 + c0 + 1] = acc[nf][3];
        }
        __syncthreads();
    }

    // ---------------- fused gate epilogue ----------------
    if (tid < 256) {
        const int b   = tid >> 2;
        const int jl0 = (tid & 3) * 4;

        float4 hp4 = make_float4(0.f, 0.f, 0.f, 0.f);
        if (s > 0)
            hp4 = *(const float4*)&Y[(size_t)b * bStride + (size_t)tprev * tStride + j0 + jl0];

        float hn[4];
        __nv_bfloat16 hh[4], hl[4];
        int tok = 0;
        if (LAYER == 0) tok = xtok[b * TT + t_x];

#pragma unroll
        for (int u = 0; u < 4; ++u) {
            const int jl = jl0 + u;
            const int j  = j0 + jl;
            float gr = 0.f, gz = 0.f, gn = 0.f;
            if (s > 0) {
                gr = sG[(0 * 64 + b) * 20 + jl];
                gz = sG[(1 * 64 + b) * 20 + jl];
                gn = sG[(2 * 64 + b) * 20 + jl];
            }
            gr += bhh[dir * G3 + j];
            gz += bhh[dir * G3 + HH + j];
            gn += bhh[dir * G3 + 2 * HH + j];

            float xr, xz, xn;
            if (LAYER == 0) {
                const float* Wd = Wih0 + (size_t)dir * G3 * VV;
                const float* bd = bih0 + dir * G3;
                xr = Wd[(size_t)j * VV + tok] + bd[j];
                xz = Wd[(size_t)(HH + j) * VV + tok] + bd[HH + j];
                xn = Wd[(size_t)(2 * HH + j) * VV + tok] + bd[2 * HH + j];
            } else {
                const float* xp = g_xp1 + (((size_t)dir * TT + t_x) * BB + b) * G3;
                xr = xp[j];
                xz = xp[HH + j];
                xn = xp[2 * HH + j];
            }
            float r = 1.f / (1.f + expf(-(xr + gr)));
            float z = 1.f / (1.f + expf(-(xz + gz)));
            float n = tanhf(xn + r * gn);
            float hpv = (u == 0) ? hp4.x : (u == 1) ? hp4.y : (u == 2) ? hp4.z : hp4.w;
            float h = (1.f - z) * n + z * hpv;
            hn[u] = h;
            __nv_bfloat16 hb = __float2bfloat16(h);
            hh[u] = hb;
            hl[u] = __float2bfloat16(h - __bfloat162float(hb));
        }

        // write fp32 y
        *(float4*)&Y[(size_t)b * bStride + (size_t)t_x * tStride + j0 + jl0] =
            make_float4(hn[0], hn[1], hn[2], hn[3]);
        // write split h state for next step
        __nv_bfloat16* dh = g_hhi + ((size_t)(dir * 2 + parN)) * BB * HH + (size_t)b * HH + j0 + jl0;
        __nv_bfloat16* dl = g_hlo + ((size_t)(dir * 2 + parN)) * BB * HH + (size_t)b * HH + j0 + jl0;
#pragma unroll
        for (int u = 0; u < 4; ++u) { dh[u] = hh[u]; dl[u] = hl[u]; }
    }
}

// ---------------------------------------------------------------------------
// Layer-1 input projection GEMM on tensor cores (bf16x3 split).
//   D[i][j] = sum_k y0cat[i][k] * Wih1[dir][j][k] + bih1[dir][j]
// CTA tile 128(i) x 64(j), KC=32, double-buffered dynamic smem (60KB).
// grid (48 j, 128 i, 2 dir), block 256 (8 warps = 4m x 2n, warp tile 32x32).
// ---------------------------------------------------------------------------
#define XSA_BYTES (2 * 2 * 128 * SA_STRIDE * 2)   // 40960
#define XSB_BYTES (2 * 2 * 64 * SA_STRIDE * 2)    // 20480

__global__ __launch_bounds__(256, 1)
void xp1_mma_kernel(const float* __restrict__ bih1)
{
    extern __shared__ __align__(16) char dsm[];
    __nv_bfloat16* sA = (__nv_bfloat16*)dsm;               // [buf][hl][128][40]
    __nv_bfloat16* sB = (__nv_bfloat16*)(dsm + XSA_BYTES); // [buf][hl][64][40]

    const int j0  = blockIdx.x * 64;
    const int i0  = blockIdx.y * 128;
    const int dir = blockIdx.z;
    const int tid = threadIdx.x;
    const int wid = tid >> 5;
    const int lid = tid & 31;
    const int gid = lid >> 2;
    const int tg2 = (lid & 3) * 2;
    const int mt  = wid >> 1;     // 0..3 -> m offset mt*32
    const int nt  = wid & 1;      // 0..1 -> n offset nt*32

    const __nv_bfloat16* Bhi = g_whi + (size_t)dir * G3 * (2 * HH);
    const __nv_bfloat16* Blo = g_wlo + (size_t)dir * G3 * (2 * HH);

    float acc[2][4][4];
#pragma unroll
    for (int mf = 0; mf < 2; ++mf)
#pragma unroll
        for (int nf = 0; nf < 4; ++nf)
#pragma unroll
            for (int q = 0; q < 4; ++q) acc[mf][nf][q] = 0.f;

    // staging: A rows 0..127 via 2 slots/thread; B rows 0..63 via 1 slot
    const int a0r = tid >> 2, a1r = (tid + 256) >> 2;
    const int ap  = tid & 3;

    uint4 pa0h, pa0l, pa1h, pa1l, pbh, pbl;
    {
        pa0h = *(const uint4*)(g_yhi + (size_t)(i0 + a0r) * (2 * HH) + ap * 8);
        pa0l = *(const uint4*)(g_ylo + (size_t)(i0 + a0r) * (2 * HH) + ap * 8);
        pa1h = *(const uint4*)(g_yhi + (size_t)(i0 + a1r) * (2 * HH) + ap * 8);
        pa1l = *(const uint4*)(g_ylo + (size_t)(i0 + a1r) * (2 * HH) + ap * 8);
        pbh  = *(const uint4*)(Bhi + (size_t)(j0 + a0r) * (2 * HH) + ap * 8);
        pbl  = *(const uint4*)(Blo + (size_t)(j0 + a0r) * (2 * HH) + ap * 8);
    }

    for (int st = 0; st < 64; ++st) {
        const int p = st & 1;
        *(uint4*)(sA + ((p*2+0)*128 + a0r) * SA_STRIDE + ap * 8) = pa0h;
        *(uint4*)(sA + ((p*2+1)*128 + a0r) * SA_STRIDE + ap * 8) = pa0l;
        *(uint4*)(sA + ((p*2+0)*128 + a1r) * SA_STRIDE + ap * 8) = pa1h;
        *(uint4*)(sA + ((p*2+1)*128 + a1r) * SA_STRIDE + ap * 8) = pa1l;
        *(uint4*)(sB + ((p*2+0)*64  + a0r) * SA_STRIDE + ap * 8) = pbh;
        *(uint4*)(sB + ((p*2+1)*64  + a0r) * SA_STRIDE + ap * 8) = pbl;
        __syncthreads();

        if (st + 1 < 64) {
            const int kc = (st + 1) * 32;
            pa0h = *(const uint4*)(g_yhi + (size_t)(i0 + a0r) * (2 * HH) + kc + ap * 8);
            pa0l = *(const uint4*)(g_ylo + (size_t)(i0 + a0r) * (2 * HH) + kc + ap * 8);
            pa1h = *(const uint4*)(g_yhi + (size_t)(i0 + a1r) * (2 * HH) + kc + ap * 8);
            pa1l = *(const uint4*)(g_ylo + (size_t)(i0 + a1r) * (2 * HH) + kc + ap * 8);
            pbh  = *(const uint4*)(Bhi + (size_t)(j0 + a0r) * (2 * HH) + kc + ap * 8);
            pbl  = *(const uint4*)(Blo + (size_t)(j0 + a0r) * (2 * HH) + kc + ap * 8);
        }

#pragma unroll
        for (int kk = 0; kk < 32; kk += 16) {
            uint32_t ah[2][4], al[2][4];
#pragma unroll
            for (int mf = 0; mf < 2; ++mf) {
                const int r = mt * 32 + mf * 16 + gid;
                ah[mf][0] = *(const uint32_t*)(sA + ((p*2+0)*128 + r    ) * SA_STRIDE + kk + tg2);
                ah[mf][1] = *(const uint32_t*)(sA + ((p*2+0)*128 + r + 8) * SA_STRIDE + kk + tg2);
                ah[mf][2] = *(const uint32_t*)(sA + ((p*2+0)*128 + r    ) * SA_STRIDE + kk + tg2 + 8);
                ah[mf][3] = *(const uint32_t*)(sA + ((p*2+0)*128 + r + 8) * SA_STRIDE + kk + tg2 + 8);
                al[mf][0] = *(const uint32_t*)(sA + ((p*2+1)*128 + r    ) * SA_STRIDE + kk + tg2);
                al[mf][1] = *(const uint32_t*)(sA + ((p*2+1)*128 + r + 8) * SA_STRIDE + kk + tg2);
                al[mf][2] = *(const uint32_t*)(sA + ((p*2+1)*128 + r    ) * SA_STRIDE + kk + tg2 + 8);
                al[mf][3] = *(const uint32_t*)(sA + ((p*2+1)*128 + r + 8) * SA_STRIDE + kk + tg2 + 8);
            }
#pragma unroll
            for (int nf = 0; nf < 4; ++nf) {
                const int nr = nt * 32 + nf * 8 + gid;
                uint32_t bh0 = *(const uint32_t*)(sB + ((p*2+0)*64 + nr) * SA_STRIDE + kk + tg2);
                uint32_t bh1 = *(const uint32_t*)(sB + ((p*2+0)*64 + nr) * SA_STRIDE + kk + tg2 + 8);
                uint32_t bl0 = *(const uint32_t*)(sB + ((p*2+1)*64 + nr) * SA_STRIDE + kk + tg2);
                uint32_t bl1 = *(const uint32_t*)(sB + ((p*2+1)*64 + nr) * SA_STRIDE + kk + tg2 + 8);
                mma_bf16(acc[0][nf], ah[0][0], ah[0][1], ah[0][2], ah[0][3], bh0, bh1);
                mma_bf16(acc[1][nf], ah[1][0], ah[1][1], ah[1][2], ah[1][3], bh0, bh1);
                mma_bf16(acc[0][nf], al[0][0], al[0][1], al[0][2], al[0][3], bh0, bh1);
                mma_bf16(acc[1][nf], al[1][0], al[1][1], al[1][2], al[1][3], bh0, bh1);
                mma_bf16(acc[0][nf], ah[0][0], ah[0][1], ah[0][2], ah[0][3], bl0, bl1);
                mma_bf16(acc[1][nf], ah[1][0], ah[1][1], ah[1][2], ah[1][3], bl0, bl1);
            }
        }
        __syncthreads();
    }

    // epilogue: + bias, scatter to g_xp1[dir][t][b][j]
#pragma unroll
    for (int mf = 0; mf < 2; ++mf) {
#pragma unroll
        for (int nf = 0; nf < 4; ++nf) {
            const int j  = j0 + nt * 32 + nf * 8 + tg2;
            const float bj0 = bih1[dir * G3 + j];
            const float bj1 = bih1[dir * G3 + j + 1];
            int i = i0 + mt * 32 + mf * 16 + gid;
            {
                const int b = i >> 8, t = i & 255;
                float2 v = make_float2(acc[mf][nf][0] + bj0, acc[mf][nf][1] + bj1);
                *(float2*)&g_xp1[(((size_t)dir * TT + t) * BB + b) * G3 + j] = v;
            }
            i += 8;
            {
                const int b = i >> 8, t = i & 255;
                float2 v = make_float2(acc[mf][nf][2] + bj0, acc[mf][nf][3] + bj1);
                *(float2*)&g_xp1[(((size_t)dir * TT + t) * BB + b) * G3 + j] = v;
            }
        }
    }
}

// ---------------------------------------------------------------------------
// Final hidden-state stack
// ---------------------------------------------------------------------------
__global__ void finalize_kernel(float* __restrict__ dout)
{
    const int idx = blockIdx.x * blockDim.x + threadIdx.x;
    const int l = idx >> 16;
    const int r = idx & 65535;
    const int b = r >> 10;
    const int h = r & 1023;
    float v;
    if (l == 0)      v = g_y0f[((size_t)b * TT + (TT - 1)) * HH + h];
    else if (l == 1) v = g_y0b[((size_t)b * TT + 0) * HH + h];
    else if (l == 2) v = dout[((size_t)b * TT + (TT - 1)) * (2 * HH) + h];
    else             v = dout[((size_t)b * TT + 0) * (2 * HH) + HH + h];
    dout[(size_t)BB * TT * 2 * HH + idx] = v;
}

// ---------------------------------------------------------------------------
extern "C" void kernel_launch(void* const* d_in, const int* in_sizes, int n_in,
                              void* d_out, int out_size)
{
    (void)in_sizes; (void)n_in; (void)out_size;
    const int*   x    = (const int*)  d_in[0];
    const float* Wih0 = (const float*)d_in[1];
    const float* Whh0 = (const float*)d_in[2];
    const float* bih0 = (const float*)d_in[3];
    const float* bhh0 = (const float*)d_in[4];
    const float* Wih1 = (const float*)d_in[5];
    const float* Whh1 = (const float*)d_in[6];
    const float* bih1 = (const float*)d_in[7];
    const float* bhh1 = (const float*)d_in[8];
    float* out = (float*)d_out;

    cudaFuncSetAttribute(xp1_mma_kernel,
                         cudaFuncAttributeMaxDynamicSharedMemorySize,
                         XSA_BYTES + XSB_BYTES);

    // Weight splits (independent of everything)
    {
        const size_t nw = (size_t)2 * 2 * G3 * HH;
        split_whh_kernel<<<(unsigned)((nw + 255) / 256), 256>>>(Whh0, Whh1);
        const size_t ni = (size_t)2 * G3 * 2 * HH;
        split_wih1_kernel<<<(unsigned)((ni + 255) / 256), 256>>>(Wih1);
    }

    dim3 sgrid(64, 2, 1);

    // Layer 0 recurrence (tensor cores), both directions per step
    for (int s = 0; s < TT; ++s)
        gru_step_mma<0><<<sgrid, 384>>>(bhh0, Wih0, bih0, x, out, s);

    // Split layer-0 outputs into hi/lo bf16
    {
        const size_t n = (size_t)BB * TT * 2 * HH;
        split_y_kernel<<<(unsigned)((n + 255) / 256), 256>>>();
    }

    // Layer-1 input projection (tensor cores)
    xp1_mma_kernel<<<dim3(48, 128, 2), 256, XSA_BYTES + XSB_BYTES>>>(bih1);

    // Layer 1 recurrence, writes straight into d_out
    for (int s = 0; s < TT; ++s)
        gru_step_mma<1><<<sgrid, 384>>>(bhh1, (const float*)0, (const float*)0, x, out, s);

    // Hidden-state stack
    finalize_kernel<<<1024, 256>>>(out);
}

// round 13
// speedup vs baseline: 2.1728x; 1.1259x over previous
#include <cuda_runtime.h>
#include <cuda_bf16.h>
#include <math.h>
#include <stdint.h>

// Problem constants
#define BB   64      // batch
#define TT   256     // time
#define HH   1024    // hidden
#define G3   3072    // 3*H
#define VV   128     // vocab

// ---------------------------------------------------------------------------
// Device-global scratch (allocation-free workaround)
// ---------------------------------------------------------------------------
__device__ __align__(16) float g_y0f[(size_t)BB * TT * HH];     // layer0 fwd y [b][t][h]
__device__ __align__(16) float g_y0b[(size_t)BB * TT * HH];     // layer0 bwd y [b][t][h]
__device__ __align__(16) float g_xp1[(size_t)2 * TT * BB * G3]; // layer1 x-proj [dir][t][b][3H]
__device__ __align__(16) __nv_bfloat16 g_yhi[(size_t)BB * TT * 2 * HH]; // y0cat hi
__device__ __align__(16) __nv_bfloat16 g_ylo[(size_t)BB * TT * 2 * HH]; // y0cat lo
__device__ __align__(16) __nv_bfloat16 g_whi[(size_t)2 * G3 * 2 * HH];  // Wih1 hi
__device__ __align__(16) __nv_bfloat16 g_wlo[(size_t)2 * G3 * 2 * HH];  // Wih1 lo
__device__ __align__(16) __nv_bfloat16 g_whh_hi[(size_t)2 * 2 * G3 * HH]; // Whh hi [layer][dir][3072][1024]
__device__ __align__(16) __nv_bfloat16 g_whh_lo[(size_t)2 * 2 * G3 * HH]; // Whh lo
__device__ __align__(16) __nv_bfloat16 g_hhi[(size_t)2 * 2 * BB * HH];  // h hi [dir][parity][64][1024]
__device__ __align__(16) __nv_bfloat16 g_hlo[(size_t)2 * 2 * BB * HH];  // h lo
__device__ unsigned g_bar[2][32];                                        // per-dir barrier (padded)

// ---------------------------------------------------------------------------
// PTX helpers
// ---------------------------------------------------------------------------
__device__ __forceinline__ void mma_bf16(float d[4],
                                         uint32_t a0, uint32_t a1, uint32_t a2, uint32_t a3,
                                         uint32_t b0, uint32_t b1)
{
    asm volatile(
        "mma.sync.aligned.m16n8k16.row.col.f32.bf16.bf16.f32 "
        "{%0,%1,%2,%3}, {%4,%5,%6,%7}, {%8,%9}, {%0,%1,%2,%3};\n"
        : "+f"(d[0]), "+f"(d[1]), "+f"(d[2]), "+f"(d[3])
        : "r"(a0), "r"(a1), "r"(a2), "r"(a3), "r"(b0), "r"(b1));
}

__device__ __forceinline__ void ldsm_x4(uint32_t& r0, uint32_t& r1, uint32_t& r2, uint32_t& r3,
                                        uint32_t addr)
{
    asm volatile("ldmatrix.sync.aligned.m8n8.x4.shared.b16 {%0,%1,%2,%3}, [%4];"
                 : "=r"(r0), "=r"(r1), "=r"(r2), "=r"(r3) : "r"(addr));
}

__device__ __forceinline__ uint32_t smem_u32(const void* p) {
    uint32_t a;
    asm("{ .reg .u64 t; cvta.to.shared.u64 t, %1; cvt.u32.u64 %0, t; }" : "=r"(a) : "l"(p));
    return a;
}

__device__ __forceinline__ uint4 ldg_cg(const void* p) {
    uint4 v;
    asm volatile("ld.global.cg.v4.u32 {%0,%1,%2,%3}, [%4];"
                 : "=r"(v.x), "=r"(v.y), "=r"(v.z), "=r"(v.w) : "l"(p));
    return v;
}

__device__ __forceinline__ unsigned ldg_acq(const unsigned* p) {
    unsigned v;
    asm volatile("ld.global.acquire.gpu.u32 %0, [%1];" : "=r"(v) : "l"(p) : "memory");
    return v;
}

// ---------------------------------------------------------------------------
// Split kernels (fp32 -> hi/lo bf16)
// ---------------------------------------------------------------------------
__global__ void split_whh_kernel(const float* __restrict__ Whh0,
                                 const float* __restrict__ Whh1)
{
    const size_t idx = (size_t)blockIdx.x * 256 + threadIdx.x;
    const size_t per_layer = (size_t)2 * G3 * HH;
    if (idx >= 2 * per_layer) return;
    float w = (idx < per_layer) ? Whh0[idx] : Whh1[idx - per_layer];
    __nv_bfloat16 h = __float2bfloat16(w);
    g_whh_hi[idx] = h;
    g_whh_lo[idx] = __float2bfloat16(w - __bfloat162float(h));
}

__global__ void split_wih1_kernel(const float* __restrict__ Wih1)
{
    const size_t idx = (size_t)blockIdx.x * 256 + threadIdx.x;
    if (idx >= (size_t)2 * G3 * 2 * HH) return;
    float w = Wih1[idx];
    __nv_bfloat16 h = __float2bfloat16(w);
    g_whi[idx] = h;
    g_wlo[idx] = __float2bfloat16(w - __bfloat162float(h));
}

__global__ void split_y_kernel()
{
    const size_t idx = (size_t)blockIdx.x * 256 + threadIdx.x;
    if (idx >= (size_t)BB * TT * 2 * HH) return;
    const size_t i = idx >> 11;
    const int    k = (int)(idx & 2047);
    float v = (k < HH) ? g_y0f[i * HH + k] : g_y0b[i * HH + (k - HH)];
    __nv_bfloat16 h = __float2bfloat16(v);
    g_yhi[idx] = h;
    g_ylo[idx] = __float2bfloat16(v - __bfloat162float(h));
}

__global__ void reset_bar_kernel()
{
    if (threadIdx.x < 2) g_bar[threadIdx.x][0] = 0u;
    __threadfence();
}

// ---------------------------------------------------------------------------
// Persistent GRU layer kernel (all 256 steps in one launch).
// grid (64, 2): x = j-tile (16 cols), y = dir. 128 CTAs, 1 CTA/SM
// (smem-forced), single wave on 148+ SMs -> all co-resident, so the
// per-direction grid barrier (monotonic counter, release-store/acquire-load)
// is deadlock-free. Whh split weights live in smem the whole kernel (192KB).
// block = 384 (12 warps = 4 m-tiles x 3 gates).
// ---------------------------------------------------------------------------
#define SBW_PAD   1032
#define SBW_BYTES (2 * 48 * SBW_PAD * 2)      // 198144
#define SAP_BYTES (2 * 2 * 64 * 40 * 2)       // 20480
#define SMEM_PERS (SBW_BYTES + SAP_BYTES)     // 218624

template <int LAYER>
__global__ __launch_bounds__(384, 1)
void gru_persist(const float* __restrict__ bhh,    // [2][3072] (this layer)
                 const float* __restrict__ Wih0,   // [2][3072][128] (layer 0 only)
                 const float* __restrict__ bih0,   // [2][3072]      (layer 0 only)
                 const int*   __restrict__ xtok,   // [64][256]
                 float* __restrict__ dout)
{
    extern __shared__ __align__(16) char dsm[];
    __nv_bfloat16* sBw = (__nv_bfloat16*)dsm;               // [hl][48][1032]
    __nv_bfloat16* sA  = (__nv_bfloat16*)(dsm + SBW_BYTES); // [buf][hl][64][40]
    float*         sG  = (float*)(dsm + SBW_BYTES);         // alias sA: [3][64][20]

    const int dir = blockIdx.y;
    const int j0  = blockIdx.x * 16;
    const int tid = threadIdx.x;
    const int wid = tid >> 5, lid = tid & 31;
    const int gid = lid >> 2, tg2 = (lid & 3) * 2;
    const int mt  = wid & 3;      // m-tile (batches mt*16..+15)
    const int gg  = wid >> 2;     // gate 0..2

    float* Y; int tStride, bStride;
    if (LAYER == 0) { Y = (dir ? g_y0b : g_y0f); tStride = HH;     bStride = TT * HH;     }
    else            { Y = dout + (dir ? HH : 0); tStride = 2 * HH; bStride = TT * 2 * HH; }

    // ---- load persistent weight tile into smem (once) ----
    {
        const __nv_bfloat16* Bhi = g_whh_hi + ((size_t)(LAYER * 2 + dir)) * G3 * HH;
        const __nv_bfloat16* Blo = g_whh_lo + ((size_t)(LAYER * 2 + dir)) * G3 * HH;
        const int r    = tid >> 3;           // 0..47
        const int c0   = (tid & 7) * 128;
        const int grow = (r >> 4) * HH + j0 + (r & 15);
#pragma unroll
        for (int u = 0; u < 128; u += 8) {
            *(uint4*)(sBw + (size_t)r * SBW_PAD + c0 + u) =
                *(const uint4*)(Bhi + (size_t)grow * HH + c0 + u);
            *(uint4*)(sBw + (size_t)(48 + r) * SBW_PAD + c0 + u) =
                *(const uint4*)(Blo + (size_t)grow * HH + c0 + u);
        }
    }
    __syncthreads();

    // ---- ldmatrix per-lane base offsets ----
    const int lrow = ((lid >> 3) & 1) * 8 + (lid & 7);
    const int lcol = (lid >> 4) * 8;
    const uint32_t sA_u = smem_u32(sA);
    const uint32_t sB_u = smem_u32(sBw);
    const uint32_t aOff   = (uint32_t)((mt * 16 + lrow) * 40 + lcol) * 2;
    const uint32_t bOffHi = sB_u + (uint32_t)((gg * 16 + lrow) * SBW_PAD + lcol) * 2;
    const uint32_t bOffLo = sB_u + (uint32_t)((48 + gg * 16 + lrow) * SBW_PAD + lcol) * 2;

    // ---- epilogue per-thread constants ----
    // cbr/cbz may fold bih0 (additive inside sigmoid). cbn holds ONLY bhh's
    // n-gate bias (it is multiplied by r); bih0's n bias goes in cxn, which
    // is added OUTSIDE the r*(...) term.  (R12 bug: bin was inside r*().)
    const int eb  = tid >> 2;          // batch (tid<256)
    const int jl0 = (tid & 3) * 4;
    float cbr[4], cbz[4], cbn[4], cxn[4];
    if (tid < 256) {
#pragma unroll
        for (int u = 0; u < 4; ++u) {
            const int j = j0 + jl0 + u;
            float br = bhh[dir * G3 + j];
            float bz = bhh[dir * G3 + HH + j];
            float bn = bhh[dir * G3 + 2 * HH + j];
            float xn_b = 0.f;
            if (LAYER == 0) {
                br  += bih0[dir * G3 + j];
                bz  += bih0[dir * G3 + HH + j];
                xn_b = bih0[dir * G3 + 2 * HH + j];   // stays outside r*()
            }
            cbr[u] = br; cbz[u] = bz; cbn[u] = bn; cxn[u] = xn_b;
        }
    }

    // A staging roles
    const int  arow = tid >> 2;
    const int  ap8  = (tid & 3) * 8;
    const bool doA  = (tid < 256);

    float hp[4] = {0.f, 0.f, 0.f, 0.f};

    for (int s = 0; s < TT; ++s) {
        const int t_x  = dir ? (TT - 1 - s) : s;
        const int par  = s & 1;
        const int parN = (s + 1) & 1;

        float acc[2][4];
#pragma unroll
        for (int nf = 0; nf < 2; ++nf)
#pragma unroll
            for (int q = 0; q < 4; ++q) acc[nf][q] = 0.f;

        if (s > 0) {
            // wait for all CTAs of this dir to finish step s-1 (acquire)
            if (tid == 0) {
                const unsigned target = 64u * (unsigned)s;
                while (ldg_acq(&g_bar[dir][0]) < target) __nanosleep(128);
            }
            __syncthreads();

            const __nv_bfloat16* Ahi = g_hhi + ((size_t)(dir * 2 + par)) * BB * HH;
            const __nv_bfloat16* Alo = g_hlo + ((size_t)(dir * 2 + par)) * BB * HH;

            uint4 pah, pal;
            if (doA) {
                pah = ldg_cg(Ahi + (size_t)arow * HH + ap8);
                pal = ldg_cg(Alo + (size_t)arow * HH + ap8);
            }

            for (int st = 0; st < 32; ++st) {
                const int p = st & 1;
                if (doA) {
                    *(uint4*)(sA + ((p * 2 + 0) * 64 + arow) * 40 + ap8) = pah;
                    *(uint4*)(sA + ((p * 2 + 1) * 64 + arow) * 40 + ap8) = pal;
                }
                __syncthreads();

                if (doA && st + 1 < 32) {
                    const int kc1 = (st + 1) * 32;
                    pah = ldg_cg(Ahi + (size_t)arow * HH + kc1 + ap8);
                    pal = ldg_cg(Alo + (size_t)arow * HH + kc1 + ap8);
                }

                const int kc = st * 32;
                const uint32_t aHi = sA_u + (uint32_t)(p * 2 + 0) * (64 * 40 * 2) + aOff;
                const uint32_t aLo = sA_u + (uint32_t)(p * 2 + 1) * (64 * 40 * 2) + aOff;
#pragma unroll
                for (int kk = 0; kk < 32; kk += 16) {
                    uint32_t ah0, ah1, ah2, ah3, al0, al1, al2, al3;
                    uint32_t bh0, bh1, bh2, bh3, bl0, bl1, bl2, bl3;
                    ldsm_x4(ah0, ah1, ah2, ah3, aHi + kk * 2);
                    ldsm_x4(al0, al1, al2, al3, aLo + kk * 2);
                    ldsm_x4(bh0, bh1, bh2, bh3, bOffHi + (kc + kk) * 2);
                    ldsm_x4(bl0, bl1, bl2, bl3, bOffLo + (kc + kk) * 2);
                    // nf=0 uses (bX0, bX2); nf=1 uses (bX1, bX3)
                    mma_bf16(acc[0], ah0, ah1, ah2, ah3, bh0, bh2);
                    mma_bf16(acc[0], al0, al1, al2, al3, bh0, bh2);
                    mma_bf16(acc[0], ah0, ah1, ah2, ah3, bl0, bl2);
                    mma_bf16(acc[1], ah0, ah1, ah2, ah3, bh1, bh3);
                    mma_bf16(acc[1], al0, al1, al2, al3, bh1, bh3);
                    mma_bf16(acc[1], ah0, ah1, ah2, ah3, bl1, bl3);
                }
                __syncthreads();
            }

            // gate exchange through smem (aliases sA; last loop iter ended in sync)
            const int r0 = mt * 16 + gid;
#pragma unroll
            for (int nf = 0; nf < 2; ++nf) {
                const int c0 = nf * 8 + tg2;
                sG[(gg * 64 + r0    ) * 20 + c0    ] = acc[nf][0];
                sG[(gg * 64 + r0    ) * 20 + c0 + 1] = acc[nf][1];
                sG[(gg * 64 + r0 + 8) * 20 + c0    ] = acc[nf][2];
                sG[(gg * 64 + r0 + 8) * 20 + c0 + 1] = acc[nf][3];
            }
            __syncthreads();
        }

        // ---------------- fused gate epilogue ----------------
        if (tid < 256) {
            float xr[4], xz[4], xn[4];
            if (LAYER == 0) {
                const int tok = xtok[eb * TT + t_x];
                const float* Wd = Wih0 + (size_t)dir * G3 * VV + tok;
#pragma unroll
                for (int u = 0; u < 4; ++u) {
                    const int j = j0 + jl0 + u;
                    xr[u] = Wd[(size_t)j * VV];
                    xz[u] = Wd[(size_t)(HH + j) * VV];
                    xn[u] = Wd[(size_t)(2 * HH + j) * VV] + cxn[u];
                }
            } else {
                const float* xp = g_xp1 + (((size_t)dir * TT + t_x) * BB + eb) * G3 + j0 + jl0;
                float4 v0 = *(const float4*)(xp);
                float4 v1 = *(const float4*)(xp + HH);
                float4 v2 = *(const float4*)(xp + 2 * HH);
                xr[0] = v0.x; xr[1] = v0.y; xr[2] = v0.z; xr[3] = v0.w;
                xz[0] = v1.x; xz[1] = v1.y; xz[2] = v1.z; xz[3] = v1.w;
                xn[0] = v2.x; xn[1] = v2.y; xn[2] = v2.z; xn[3] = v2.w;
            }

            float hn[4];
            __nv_bfloat16 hh[4], hl[4];
#pragma unroll
            for (int u = 0; u < 4; ++u) {
                const int jl = jl0 + u;
                float gr = 0.f, gz = 0.f, gn = 0.f;
                if (s > 0) {
                    gr = sG[(0 * 64 + eb) * 20 + jl];
                    gz = sG[(1 * 64 + eb) * 20 + jl];
                    gn = sG[(2 * 64 + eb) * 20 + jl];
                }
                float r = 1.f / (1.f + expf(-(xr[u] + gr + cbr[u])));
                float z = 1.f / (1.f + expf(-(xz[u] + gz + cbz[u])));
                float n = tanhf(xn[u] + r * (gn + cbn[u]));
                float h = (1.f - z) * n + z * hp[u];
                hn[u] = h; hp[u] = h;
                __nv_bfloat16 hb = __float2bfloat16(h);
                hh[u] = hb;
                hl[u] = __float2bfloat16(h - __bfloat162float(hb));
            }

            // y output (fp32)
            *(float4*)&Y[(size_t)eb * bStride + (size_t)t_x * tStride + j0 + jl0] =
                make_float4(hn[0], hn[1], hn[2], hn[3]);
            // split h state for next step (other CTAs read via .cg)
            __nv_bfloat16* dh = g_hhi + ((size_t)(dir * 2 + parN)) * BB * HH + (size_t)eb * HH + j0 + jl0;
            __nv_bfloat16* dl = g_hlo + ((size_t)(dir * 2 + parN)) * BB * HH + (size_t)eb * HH + j0 + jl0;
            uint2 ph, pl;
            ph.x = ((uint32_t)__bfloat16_as_ushort(hh[1]) << 16) | __bfloat16_as_ushort(hh[0]);
            ph.y = ((uint32_t)__bfloat16_as_ushort(hh[3]) << 16) | __bfloat16_as_ushort(hh[2]);
            pl.x = ((uint32_t)__bfloat16_as_ushort(hl[1]) << 16) | __bfloat16_as_ushort(hl[0]);
            pl.y = ((uint32_t)__bfloat16_as_ushort(hl[3]) << 16) | __bfloat16_as_ushort(hl[2]);
            *(uint2*)dh = ph;
            *(uint2*)dl = pl;
        }

        // publish: all writes visible, then arrive (release)
        __threadfence();
        __syncthreads();
        if (tid == 0) atomicAdd(&g_bar[dir][0], 1u);
    }
}

// ---------------------------------------------------------------------------
// Layer-1 input projection GEMM on tensor cores (bf16x3 split).
// ---------------------------------------------------------------------------
#define SA_STRIDE 40
#define XSA_BYTES (2 * 2 * 128 * SA_STRIDE * 2)   // 40960
#define XSB_BYTES (2 * 2 * 64 * SA_STRIDE * 2)    // 20480

__global__ __launch_bounds__(256, 1)
void xp1_mma_kernel(const float* __restrict__ bih1)
{
    extern __shared__ __align__(16) char dsm[];
    __nv_bfloat16* sA = (__nv_bfloat16*)dsm;               // [buf][hl][128][40]
    __nv_bfloat16* sB = (__nv_bfloat16*)(dsm + XSA_BYTES); // [buf][hl][64][40]

    const int j0  = blockIdx.x * 64;
    const int i0  = blockIdx.y * 128;
    const int dir = blockIdx.z;
    const int tid = threadIdx.x;
    const int wid = tid >> 5;
    const int lid = tid & 31;
    const int gid = lid >> 2;
    const int tg2 = (lid & 3) * 2;
    const int mt  = wid >> 1;
    const int nt  = wid & 1;

    const __nv_bfloat16* Bhi = g_whi + (size_t)dir * G3 * (2 * HH);
    const __nv_bfloat16* Blo = g_wlo + (size_t)dir * G3 * (2 * HH);

    float acc[2][4][4];
#pragma unroll
    for (int mf = 0; mf < 2; ++mf)
#pragma unroll
        for (int nf = 0; nf < 4; ++nf)
#pragma unroll
            for (int q = 0; q < 4; ++q) acc[mf][nf][q] = 0.f;

    const int a0r = tid >> 2, a1r = (tid + 256) >> 2;
    const int ap  = tid & 3;

    uint4 pa0h, pa0l, pa1h, pa1l, pbh, pbl;
    {
        pa0h = *(const uint4*)(g_yhi + (size_t)(i0 + a0r) * (2 * HH) + ap * 8);
        pa0l = *(const uint4*)(g_ylo + (size_t)(i0 + a0r) * (2 * HH) + ap * 8);
        pa1h = *(const uint4*)(g_yhi + (size_t)(i0 + a1r) * (2 * HH) + ap * 8);
        pa1l = *(const uint4*)(g_ylo + (size_t)(i0 + a1r) * (2 * HH) + ap * 8);
        pbh  = *(const uint4*)(Bhi + (size_t)(j0 + a0r) * (2 * HH) + ap * 8);
        pbl  = *(const uint4*)(Blo + (size_t)(j0 + a0r) * (2 * HH) + ap * 8);
    }

    for (int st = 0; st < 64; ++st) {
        const int p = st & 1;
        *(uint4*)(sA + ((p*2+0)*128 + a0r) * SA_STRIDE + ap * 8) = pa0h;
        *(uint4*)(sA + ((p*2+1)*128 + a0r) * SA_STRIDE + ap * 8) = pa0l;
        *(uint4*)(sA + ((p*2+0)*128 + a1r) * SA_STRIDE + ap * 8) = pa1h;
        *(uint4*)(sA + ((p*2+1)*128 + a1r) * SA_STRIDE + ap * 8) = pa1l;
        *(uint4*)(sB + ((p*2+0)*64  + a0r) * SA_STRIDE + ap * 8) = pbh;
        *(uint4*)(sB + ((p*2+1)*64  + a0r) * SA_STRIDE + ap * 8) = pbl;
        __syncthreads();

        if (st + 1 < 64) {
            const int kc = (st + 1) * 32;
            pa0h = *(const uint4*)(g_yhi + (size_t)(i0 + a0r) * (2 * HH) + kc + ap * 8);
            pa0l = *(const uint4*)(g_ylo + (size_t)(i0 + a0r) * (2 * HH) + kc + ap * 8);
            pa1h = *(const uint4*)(g_yhi + (size_t)(i0 + a1r) * (2 * HH) + kc + ap * 8);
            pa1l = *(const uint4*)(g_ylo + (size_t)(i0 + a1r) * (2 * HH) + kc + ap * 8);
            pbh  = *(const uint4*)(Bhi + (size_t)(j0 + a0r) * (2 * HH) + kc + ap * 8);
            pbl  = *(const uint4*)(Blo + (size_t)(j0 + a0r) * (2 * HH) + kc + ap * 8);
        }

#pragma unroll
        for (int kk = 0; kk < 32; kk += 16) {
            uint32_t ah[2][4], al[2][4];
#pragma unroll
            for (int mf = 0; mf < 2; ++mf) {
                const int r = mt * 32 + mf * 16 + gid;
                ah[mf][0] = *(const uint32_t*)(sA + ((p*2+0)*128 + r    ) * SA_STRIDE + kk + tg2);
                ah[mf][1] = *(const uint32_t*)(sA + ((p*2+0)*128 + r + 8) * SA_STRIDE + kk + tg2);
                ah[mf][2] = *(const uint32_t*)(sA + ((p*2+0)*128 + r    ) * SA_STRIDE + kk + tg2 + 8);
                ah[mf][3] = *(const uint32_t*)(sA + ((p*2+0)*128 + r + 8) * SA_STRIDE + kk + tg2 + 8);
                al[mf][0] = *(const uint32_t*)(sA + ((p*2+1)*128 + r    ) * SA_STRIDE + kk + tg2);
                al[mf][1] = *(const uint32_t*)(sA + ((p*2+1)*128 + r + 8) * SA_STRIDE + kk + tg2);
                al[mf][2] = *(const uint32_t*)(sA + ((p*2+1)*128 + r    ) * SA_STRIDE + kk + tg2 + 8);
                al[mf][3] = *(const uint32_t*)(sA + ((p*2+1)*128 + r + 8) * SA_STRIDE + kk + tg2 + 8);
            }
#pragma unroll
            for (int nf = 0; nf < 4; ++nf) {
                const int nr = nt * 32 + nf * 8 + gid;
                uint32_t bh0 = *(const uint32_t*)(sB + ((p*2+0)*64 + nr) * SA_STRIDE + kk + tg2);
                uint32_t bh1 = *(const uint32_t*)(sB + ((p*2+0)*64 + nr) * SA_STRIDE + kk + tg2 + 8);
                uint32_t bl0 = *(const uint32_t*)(sB + ((p*2+1)*64 + nr) * SA_STRIDE + kk + tg2);
                uint32_t bl1 = *(const uint32_t*)(sB + ((p*2+1)*64 + nr) * SA_STRIDE + kk + tg2 + 8);
                mma_bf16(acc[0][nf], ah[0][0], ah[0][1], ah[0][2], ah[0][3], bh0, bh1);
                mma_bf16(acc[1][nf], ah[1][0], ah[1][1], ah[1][2], ah[1][3], bh0, bh1);
                mma_bf16(acc[0][nf], al[0][0], al[0][1], al[0][2], al[0][3], bh0, bh1);
                mma_bf16(acc[1][nf], al[1][0], al[1][1], al[1][2], al[1][3], bh0, bh1);
                mma_bf16(acc[0][nf], ah[0][0], ah[0][1], ah[0][2], ah[0][3], bl0, bl1);
                mma_bf16(acc[1][nf], ah[1][0], ah[1][1], ah[1][2], ah[1][3], bl0, bl1);
            }
        }
        __syncthreads();
    }

#pragma unroll
    for (int mf = 0; mf < 2; ++mf) {
#pragma unroll
        for (int nf = 0; nf < 4; ++nf) {
            const int j  = j0 + nt * 32 + nf * 8 + tg2;
            const float bj0 = bih1[dir * G3 + j];
            const float bj1 = bih1[dir * G3 + j + 1];
            int i = i0 + mt * 32 + mf * 16 + gid;
            {
                const int b = i >> 8, t = i & 255;
                float2 v = make_float2(acc[mf][nf][0] + bj0, acc[mf][nf][1] + bj1);
                *(float2*)&g_xp1[(((size_t)dir * TT + t) * BB + b) * G3 + j] = v;
            }
            i += 8;
            {
                const int b = i >> 8, t = i & 255;
                float2 v = make_float2(acc[mf][nf][2] + bj0, acc[mf][nf][3] + bj1);
                *(float2*)&g_xp1[(((size_t)dir * TT + t) * BB + b) * G3 + j] = v;
            }
        }
    }
}

// ---------------------------------------------------------------------------
// Final hidden-state stack
// ---------------------------------------------------------------------------
__global__ void finalize_kernel(float* __restrict__ dout)
{
    const int idx = blockIdx.x * blockDim.x + threadIdx.x;
    const int l = idx >> 16;
    const int r = idx & 65535;
    const int b = r >> 10;
    const int h = r & 1023;
    float v;
    if (l == 0)      v = g_y0f[((size_t)b * TT + (TT - 1)) * HH + h];
    else if (l == 1) v = g_y0b[((size_t)b * TT + 0) * HH + h];
    else if (l == 2) v = dout[((size_t)b * TT + (TT - 1)) * (2 * HH) + h];
    else             v = dout[((size_t)b * TT + 0) * (2 * HH) + HH + h];
    dout[(size_t)BB * TT * 2 * HH + idx] = v;
}

// ---------------------------------------------------------------------------
extern "C" void kernel_launch(void* const* d_in, const int* in_sizes, int n_in,
                              void* d_out, int out_size)
{
    (void)in_sizes; (void)n_in; (void)out_size;
    const int*   x    = (const int*)  d_in[0];
    const float* Wih0 = (const float*)d_in[1];
    const float* Whh0 = (const float*)d_in[2];
    const float* bih0 = (const float*)d_in[3];
    const float* bhh0 = (const float*)d_in[4];
    const float* Wih1 = (const float*)d_in[5];
    const float* Whh1 = (const float*)d_in[6];
    const float* bih1 = (const float*)d_in[7];
    const float* bhh1 = (const float*)d_in[8];
    float* out = (float*)d_out;

    cudaFuncSetAttribute(xp1_mma_kernel,
                         cudaFuncAttributeMaxDynamicSharedMemorySize,
                         XSA_BYTES + XSB_BYTES);
    cudaFuncSetAttribute(gru_persist<0>,
                         cudaFuncAttributeMaxDynamicSharedMemorySize, SMEM_PERS);
    cudaFuncSetAttribute(gru_persist<1>,
                         cudaFuncAttributeMaxDynamicSharedMemorySize, SMEM_PERS);

    // Weight splits
    {
        const size_t nw = (size_t)2 * 2 * G3 * HH;
        split_whh_kernel<<<(unsigned)((nw + 255) / 256), 256>>>(Whh0, Whh1);
        const size_t ni = (size_t)2 * G3 * 2 * HH;
        split_wih1_kernel<<<(unsigned)((ni + 255) / 256), 256>>>(Wih1);
    }

    // Layer 0 recurrence (persistent, both dirs)
    reset_bar_kernel<<<1, 32>>>();
    gru_persist<0><<<dim3(64, 2), 384, SMEM_PERS>>>(bhh0, Wih0, bih0, x, out);

    // Split layer-0 outputs into hi/lo bf16
    {
        const size_t n = (size_t)BB * TT * 2 * HH;
        split_y_kernel<<<(unsigned)((n + 255) / 256), 256>>>();
    }

    // Layer-1 input projection (tensor cores)
    xp1_mma_kernel<<<dim3(48, 128, 2), 256, XSA_BYTES + XSB_BYTES>>>(bih1);

    // Layer 1 recurrence (persistent, both dirs) -> writes into d_out
    reset_bar_kernel<<<1, 32>>>();
    gru_persist<1><<<dim3(64, 2), 384, SMEM_PERS>>>(bhh1, (const float*)0, (const float*)0, x, out);

    // Hidden-state stack
    finalize_kernel<<<1024, 256>>>(out);
}

// round 15
// speedup vs baseline: 2.4531x; 1.1290x over previous
#include <cuda_runtime.h>
#include <cuda_bf16.h>
#include <math.h>
#include <stdint.h>

// Problem constants
#define BB   64      // batch
#define TT   256     // time
#define HH   1024    // hidden
#define G3   3072    // 3*H
#define VV   128     // vocab

// ---------------------------------------------------------------------------
// Device-global scratch (allocation-free workaround)
// ---------------------------------------------------------------------------
__device__ __align__(16) float g_xp1[(size_t)2 * TT * BB * G3]; // layer1 x-proj [dir][t][b][3H]
__device__ __align__(16) __nv_bfloat16 g_yhi[(size_t)BB * TT * 2 * HH]; // y0cat hi [b*256+t][2048]
__device__ __align__(16) __nv_bfloat16 g_ylo[(size_t)BB * TT * 2 * HH]; // y0cat lo
__device__ __align__(16) __nv_bfloat16 g_whi[(size_t)2 * G3 * 2 * HH];  // Wih1 hi
__device__ __align__(16) __nv_bfloat16 g_wlo[(size_t)2 * G3 * 2 * HH];  // Wih1 lo
__device__ __align__(16) __nv_bfloat16 g_whh_hi[(size_t)2 * 2 * G3 * HH]; // Whh hi [layer][dir][3072][1024]
__device__ __align__(16) __nv_bfloat16 g_whh_lo[(size_t)2 * 2 * G3 * HH]; // Whh lo
__device__ __align__(16) __nv_bfloat16 g_hhi[(size_t)2 * 2 * BB * HH];  // h hi [dir][parity][64][1024] (layer1)
__device__ __align__(16) __nv_bfloat16 g_hlo[(size_t)2 * 2 * BB * HH];  // h lo (layer1)
__device__ unsigned g_bar[2][32];                                        // per-dir barrier (padded)

// ---------------------------------------------------------------------------
// PTX helpers
// ---------------------------------------------------------------------------
__device__ __forceinline__ void mma_bf16(float d[4],
                                         uint32_t a0, uint32_t a1, uint32_t a2, uint32_t a3,
                                         uint32_t b0, uint32_t b1)
{
    asm volatile(
        "mma.sync.aligned.m16n8k16.row.col.f32.bf16.bf16.f32 "
        "{%0,%1,%2,%3}, {%4,%5,%6,%7}, {%8,%9}, {%0,%1,%2,%3};\n"
        : "+f"(d[0]), "+f"(d[1]), "+f"(d[2]), "+f"(d[3])
        : "r"(a0), "r"(a1), "r"(a2), "r"(a3), "r"(b0), "r"(b1));
}

__device__ __forceinline__ void ldsm_x4(uint32_t& r0, uint32_t& r1, uint32_t& r2, uint32_t& r3,
                                        uint32_t addr)
{
    asm volatile("ldmatrix.sync.aligned.m8n8.x4.shared.b16 {%0,%1,%2,%3}, [%4];"
                 : "=r"(r0), "=r"(r1), "=r"(r2), "=r"(r3) : "r"(addr));
}

__device__ __forceinline__ uint32_t smem_u32(const void* p) {
    uint32_t a;
    asm("{ .reg .u64 t; cvta.to.shared.u64 t, %1; cvt.u32.u64 %0, t; }" : "=r"(a) : "l"(p));
    return a;
}

__device__ __forceinline__ uint4 ldg_cg(const void* p) {
    uint4 v;
    asm volatile("ld.global.cg.v4.u32 {%0,%1,%2,%3}, [%4];"
                 : "=r"(v.x), "=r"(v.y), "=r"(v.z), "=r"(v.w) : "l"(p));
    return v;
}

__device__ __forceinline__ unsigned ldg_acq(const unsigned* p) {
    unsigned v;
    asm volatile("ld.global.acquire.gpu.u32 %0, [%1];" : "=r"(v) : "l"(p) : "memory");
    return v;
}

// ---------------------------------------------------------------------------
// Split kernels (fp32 -> hi/lo bf16)
// ---------------------------------------------------------------------------
__global__ void split_whh_kernel(const float* __restrict__ Whh0,
                                 const float* __restrict__ Whh1)
{
    const size_t idx = (size_t)blockIdx.x * 256 + threadIdx.x;
    const size_t per_layer = (size_t)2 * G3 * HH;
    if (idx >= 2 * per_layer) return;
    float w = (idx < per_layer) ? Whh0[idx] : Whh1[idx - per_layer];
    __nv_bfloat16 h = __float2bfloat16(w);
    g_whh_hi[idx] = h;
    g_whh_lo[idx] = __float2bfloat16(w - __bfloat162float(h));
}

__global__ void split_wih1_kernel(const float* __restrict__ Wih1)
{
    const size_t idx = (size_t)blockIdx.x * 256 + threadIdx.x;
    if (idx >= (size_t)2 * G3 * 2 * HH) return;
    float w = Wih1[idx];
    __nv_bfloat16 h = __float2bfloat16(w);
    g_whi[idx] = h;
    g_wlo[idx] = __float2bfloat16(w - __bfloat162float(h));
}

__global__ void reset_bar_kernel()
{
    if (threadIdx.x < 2) g_bar[threadIdx.x][0] = 0u;
    __threadfence();
}

// ---------------------------------------------------------------------------
// Persistent GRU layer kernel (all 256 steps in one launch).
// grid (64, 2): x = j-tile (16 cols), y = dir. 128 CTAs, 1 CTA/SM
// (smem-forced), single wave -> co-resident, per-dir grid barrier
// (monotonic counter, release/acquire). Whh split weights resident in smem.
// block = 384 (12 warps = 4 m-tiles x 3 gates).
// Layer0: y AND h live in g_yhi/g_ylo (split bf16); epilogue writes them,
// mainloop reads them at tprev. Layer1: y fp32 -> dout; h in parity buffers.
// ---------------------------------------------------------------------------
#define SBW_PAD   1032
#define SBW_BYTES (2 * 48 * SBW_PAD * 2)      // 198144
#define SAP_BYTES (2 * 2 * 64 * 40 * 2)       // 20480
#define SMEM_PERS (SBW_BYTES + SAP_BYTES)     // 218624

template <int LAYER>
__global__ __launch_bounds__(384, 1)
void gru_persist(const float* __restrict__ bhh,    // [2][3072] (this layer)
                 const float* __restrict__ Wih0,   // [2][3072][128] (layer 0 only)
                 const float* __restrict__ bih0,   // [2][3072]      (layer 0 only)
                 const int*   __restrict__ xtok,   // [64][256]
                 float* __restrict__ dout)
{
    extern __shared__ __align__(16) char dsm[];
    __nv_bfloat16* sBw = (__nv_bfloat16*)dsm;               // [hl][48][1032]
    __nv_bfloat16* sA  = (__nv_bfloat16*)(dsm + SBW_BYTES); // [buf][hl][64][40]
    float*         sG  = (float*)(dsm + SBW_BYTES);         // alias sA: [3][64][20]

    const int dir = blockIdx.y;
    const int j0  = blockIdx.x * 16;
    const int tid = threadIdx.x;
    const int wid = tid >> 5, lid = tid & 31;
    const int gid = lid >> 2, tg2 = (lid & 3) * 2;
    const int mt  = wid & 3;      // m-tile (batches mt*16..+15)
    const int gg  = wid >> 2;     // gate 0..2

    // ---- load persistent weight tile into smem (once) ----
    {
        const __nv_bfloat16* Bhi = g_whh_hi + ((size_t)(LAYER * 2 + dir)) * G3 * HH;
        const __nv_bfloat16* Blo = g_whh_lo + ((size_t)(LAYER * 2 + dir)) * G3 * HH;
        const int r    = tid >> 3;           // 0..47
        const int c0   = (tid & 7) * 128;
        const int grow = (r >> 4) * HH + j0 + (r & 15);
#pragma unroll
        for (int u = 0; u < 128; u += 8) {
            *(uint4*)(sBw + (size_t)r * SBW_PAD + c0 + u) =
                *(const uint4*)(Bhi + (size_t)grow * HH + c0 + u);
            *(uint4*)(sBw + (size_t)(48 + r) * SBW_PAD + c0 + u) =
                *(const uint4*)(Blo + (size_t)grow * HH + c0 + u);
        }
    }
    __syncthreads();

    // ---- ldmatrix per-lane base offsets ----
    const int lrow = ((lid >> 3) & 1) * 8 + (lid & 7);
    const int lcol = (lid >> 4) * 8;
    const uint32_t sA_u = smem_u32(sA);
    const uint32_t sB_u = smem_u32(sBw);
    const uint32_t aOff   = (uint32_t)((mt * 16 + lrow) * 40 + lcol) * 2;
    const uint32_t bOffHi = sB_u + (uint32_t)((gg * 16 + lrow) * SBW_PAD + lcol) * 2;
    const uint32_t bOffLo = sB_u + (uint32_t)((48 + gg * 16 + lrow) * SBW_PAD + lcol) * 2;

    // ---- epilogue per-thread constants ----
    // cbr/cbz fold bih0 (additive inside sigmoid); cbn = bhh n-bias only
    // (multiplied by r); bih0's n-bias (cxn) is added OUTSIDE r*().
    const int eb  = tid >> 2;          // batch (tid<256)
    const int jl0 = (tid & 3) * 4;
    float cbr[4], cbz[4], cbn[4], cxn[4];
    if (tid < 256) {
#pragma unroll
        for (int u = 0; u < 4; ++u) {
            const int j = j0 + jl0 + u;
            float br = bhh[dir * G3 + j];
            float bz = bhh[dir * G3 + HH + j];
            float bn = bhh[dir * G3 + 2 * HH + j];
            float xn_b = 0.f;
            if (LAYER == 0) {
                br  += bih0[dir * G3 + j];
                bz  += bih0[dir * G3 + HH + j];
                xn_b = bih0[dir * G3 + 2 * HH + j];
            }
            cbr[u] = br; cbz[u] = bz; cbn[u] = bn; cxn[u] = xn_b;
        }
    }

    // A staging roles
    const int  arow = tid >> 2;        // batch row 0..63
    const int  ap8  = (tid & 3) * 8;
    const bool doA  = (tid < 256);

    float hp[4] = {0.f, 0.f, 0.f, 0.f};

    for (int s = 0; s < TT; ++s) {
        const int t_x  = dir ? (TT - 1 - s) : s;
        const int tprev = dir ? (t_x + 1) : (t_x - 1);
        const int par  = s & 1;
        const int parN = (s + 1) & 1;

        // ---- prefetch x-projection (step-invariant data, overlaps barrier) ----
        float xr[4], xz[4], xn[4];
        if (tid < 256) {
            if (LAYER == 0) {
                const int tok = xtok[eb * TT + t_x];
                const float* Wd = Wih0 + (size_t)dir * G3 * VV + tok;
#pragma unroll
                for (int u = 0; u < 4; ++u) {
                    const int j = j0 + jl0 + u;
                    xr[u] = Wd[(size_t)j * VV];
                    xz[u] = Wd[(size_t)(HH + j) * VV];
                    xn[u] = Wd[(size_t)(2 * HH + j) * VV] + cxn[u];
                }
            } else {
                const float* xp = g_xp1 + (((size_t)dir * TT + t_x) * BB + eb) * G3 + j0 + jl0;
                float4 v0 = *(const float4*)(xp);
                float4 v1 = *(const float4*)(xp + HH);
                float4 v2 = *(const float4*)(xp + 2 * HH);
                xr[0] = v0.x; xr[1] = v0.y; xr[2] = v0.z; xr[3] = v0.w;
                xz[0] = v1.x; xz[1] = v1.y; xz[2] = v1.z; xz[3] = v1.w;
                xn[0] = v2.x; xn[1] = v2.y; xn[2] = v2.z; xn[3] = v2.w;
            }
        }

        float acc[2][4];
#pragma unroll
        for (int nf = 0; nf < 2; ++nf)
#pragma unroll
            for (int q = 0; q < 4; ++q) acc[nf][q] = 0.f;

        if (s > 0) {
            // wait for all CTAs of this dir to finish step s-1 (acquire)
            if (tid == 0) {
                const unsigned target = 64u * (unsigned)s;
                while (ldg_acq(&g_bar[dir][0]) < target) __nanosleep(64);
            }
            __syncthreads();

            // per-thread A row base for this step
            const __nv_bfloat16* aHiBase;
            const __nv_bfloat16* aLoBase;
            if (LAYER == 0) {
                const size_t rowoff = ((size_t)(arow * TT + tprev)) * (2 * HH) + (size_t)dir * HH;
                aHiBase = g_yhi + rowoff;
                aLoBase = g_ylo + rowoff;
            } else {
                const size_t rowoff = ((size_t)(dir * 2 + par)) * BB * HH + (size_t)arow * HH;
                aHiBase = g_hhi + rowoff;
                aLoBase = g_hlo + rowoff;
            }

            // ---- mainloop: double-buffered, ONE sync per chunk ----
            if (doA) {
                uint4 pah = ldg_cg(aHiBase + ap8);
                uint4 pal = ldg_cg(aLoBase + ap8);
                *(uint4*)(sA + (0 * 64 + arow) * 40 + ap8) = pah;     // buf0 hi
                *(uint4*)(sA + (1 * 64 + arow) * 40 + ap8) = pal;     // buf0 lo
            }
            __syncthreads();

            for (int st = 0; st < 32; ++st) {
                const int p = st & 1;
                uint4 nah, nal;
                if (doA && st < 31) {
                    const int kc1 = (st + 1) * 32;
                    nah = ldg_cg(aHiBase + kc1 + ap8);
                    nal = ldg_cg(aLoBase + kc1 + ap8);
                }

                const int kc = st * 32;
                const uint32_t aHi = sA_u + (uint32_t)(p * 2 + 0) * (64 * 40 * 2) + aOff;
                const uint32_t aLo = sA_u + (uint32_t)(p * 2 + 1) * (64 * 40 * 2) + aOff;
#pragma unroll
                for (int kk = 0; kk < 32; kk += 16) {
                    uint32_t ah0, ah1, ah2, ah3, al0, al1, al2, al3;
                    uint32_t bh0, bh1, bh2, bh3, bl0, bl1, bl2, bl3;
                    ldsm_x4(ah0, ah1, ah2, ah3, aHi + kk * 2);
                    ldsm_x4(al0, al1, al2, al3, aLo + kk * 2);
                    ldsm_x4(bh0, bh1, bh2, bh3, bOffHi + (kc + kk) * 2);
                    ldsm_x4(bl0, bl1, bl2, bl3, bOffLo + (kc + kk) * 2);
                    // nf=0 uses (bX0, bX2); nf=1 uses (bX1, bX3)
                    mma_bf16(acc[0], ah0, ah1, ah2, ah3, bh0, bh2);
                    mma_bf16(acc[0], al0, al1, al2, al3, bh0, bh2);
                    mma_bf16(acc[0], ah0, ah1, ah2, ah3, bl0, bl2);
                    mma_bf16(acc[1], ah0, ah1, ah2, ah3, bh1, bh3);
                    mma_bf16(acc[1], al0, al1, al2, al3, bh1, bh3);
                    mma_bf16(acc[1], ah0, ah1, ah2, ah3, bl1, bl3);
                }

                if (doA && st < 31) {
                    const int pn = p ^ 1;
                    *(uint4*)(sA + ((pn * 2 + 0) * 64 + arow) * 40 + ap8) = nah;
                    *(uint4*)(sA + ((pn * 2 + 1) * 64 + arow) * 40 + ap8) = nal;
                }
                __syncthreads();
            }

            // gate exchange through smem (aliases sA; all ldsm complete)
            const int r0 = mt * 16 + gid;
#pragma unroll
            for (int nf = 0; nf < 2; ++nf) {
                const int c0 = nf * 8 + tg2;
                sG[(gg * 64 + r0    ) * 20 + c0    ] = acc[nf][0];
                sG[(gg * 64 + r0    ) * 20 + c0 + 1] = acc[nf][1];
                sG[(gg * 64 + r0 + 8) * 20 + c0    ] = acc[nf][2];
                sG[(gg * 64 + r0 + 8) * 20 + c0 + 1] = acc[nf][3];
            }
            __syncthreads();
        }

        // ---------------- fused gate epilogue ----------------
        if (tid < 256) {
            float hn[4];
            __nv_bfloat16 hh[4], hl[4];
#pragma unroll
            for (int u = 0; u < 4; ++u) {
                const int jl = jl0 + u;
                float gr = 0.f, gz = 0.f, gn = 0.f;
                if (s > 0) {
                    gr = sG[(0 * 64 + eb) * 20 + jl];
                    gz = sG[(1 * 64 + eb) * 20 + jl];
                    gn = sG[(2 * 64 + eb) * 20 + jl];
                }
                float r = 1.f / (1.f + expf(-(xr[u] + gr + cbr[u])));
                float z = 1.f / (1.f + expf(-(xz[u] + gz + cbz[u])));
                float n = tanhf(xn[u] + r * (gn + cbn[u]));
                float h = (1.f - z) * n + z * hp[u];
                hn[u] = h; hp[u] = h;
                __nv_bfloat16 hb = __float2bfloat16(h);
                hh[u] = hb;
                hl[u] = __float2bfloat16(h - __bfloat162float(hb));
            }

            uint2 ph, pl;
            ph.x = ((uint32_t)__bfloat16_as_ushort(hh[1]) << 16) | __bfloat16_as_ushort(hh[0]);
            ph.y = ((uint32_t)__bfloat16_as_ushort(hh[3]) << 16) | __bfloat16_as_ushort(hh[2]);
            pl.x = ((uint32_t)__bfloat16_as_ushort(hl[1]) << 16) | __bfloat16_as_ushort(hl[0]);
            pl.y = ((uint32_t)__bfloat16_as_ushort(hl[3]) << 16) | __bfloat16_as_ushort(hl[2]);

            if (LAYER == 0) {
                // y doubles as h-state: split bf16 into g_yhi/g_ylo
                const size_t rowoff = ((size_t)(eb * TT + t_x)) * (2 * HH) + (size_t)dir * HH + j0 + jl0;
                *(uint2*)(g_yhi + rowoff) = ph;
                *(uint2*)(g_ylo + rowoff) = pl;
            } else {
                // fp32 y straight into d_out
                float* Y = dout + (dir ? HH : 0);
                *(float4*)&Y[(size_t)eb * (TT * 2 * HH) + (size_t)t_x * (2 * HH) + j0 + jl0] =
                    make_float4(hn[0], hn[1], hn[2], hn[3]);
                // split h state (parity) for next step
                const size_t rowoff = ((size_t)(dir * 2 + parN)) * BB * HH + (size_t)eb * HH + j0 + jl0;
                *(uint2*)(g_hhi + rowoff) = ph;
                *(uint2*)(g_hlo + rowoff) = pl;
            }
        }

        // publish: all writes visible, then arrive (release)
        __threadfence();
        __syncthreads();
        if (tid == 0) atomicAdd(&g_bar[dir][0], 1u);
    }
}

// ---------------------------------------------------------------------------
// Layer-1 input projection GEMM on tensor cores (bf16x3 split).
// ---------------------------------------------------------------------------
#define SA_STRIDE 40
#define XSA_BYTES (2 * 2 * 128 * SA_STRIDE * 2)   // 40960
#define XSB_BYTES (2 * 2 * 64 * SA_STRIDE * 2)    // 20480

__global__ __launch_bounds__(256, 1)
void xp1_mma_kernel(const float* __restrict__ bih1)
{
    extern __shared__ __align__(16) char dsm[];
    __nv_bfloat16* sA = (__nv_bfloat16*)dsm;               // [buf][hl][128][40]
    __nv_bfloat16* sB = (__nv_bfloat16*)(dsm + XSA_BYTES); // [buf][hl][64][40]

    const int j0  = blockIdx.x * 64;
    const int i0  = blockIdx.y * 128;
    const int dir = blockIdx.z;
    const int tid = threadIdx.x;
    const int wid = tid >> 5;
    const int lid = tid & 31;
    const int gid = lid >> 2;
    const int tg2 = (lid & 3) * 2;
    const int mt  = wid >> 1;
    const int nt  = wid & 1;

    const __nv_bfloat16* Bhi = g_whi + (size_t)dir * G3 * (2 * HH);
    const __nv_bfloat16* Blo = g_wlo + (size_t)dir * G3 * (2 * HH);

    float acc[2][4][4];
#pragma unroll
    for (int mf = 0; mf < 2; ++mf)
#pragma unroll
        for (int nf = 0; nf < 4; ++nf)
#pragma unroll
            for (int q = 0; q < 4; ++q) acc[mf][nf][q] = 0.f;

    const int a0r = tid >> 2, a1r = (tid + 256) >> 2;
    const int ap  = tid & 3;

    uint4 pa0h, pa0l, pa1h, pa1l, pbh, pbl;
    {
        pa0h = *(const uint4*)(g_yhi + (size_t)(i0 + a0r) * (2 * HH) + ap * 8);
        pa0l = *(const uint4*)(g_ylo + (size_t)(i0 + a0r) * (2 * HH) + ap * 8);
        pa1h = *(const uint4*)(g_yhi + (size_t)(i0 + a1r) * (2 * HH) + ap * 8);
        pa1l = *(const uint4*)(g_ylo + (size_t)(i0 + a1r) * (2 * HH) + ap * 8);
        pbh  = *(const uint4*)(Bhi + (size_t)(j0 + a0r) * (2 * HH) + ap * 8);
        pbl  = *(const uint4*)(Blo + (size_t)(j0 + a0r) * (2 * HH) + ap * 8);
    }

    for (int st = 0; st < 64; ++st) {
        const int p = st & 1;
        *(uint4*)(sA + ((p*2+0)*128 + a0r) * SA_STRIDE + ap * 8) = pa0h;
        *(uint4*)(sA + ((p*2+1)*128 + a0r) * SA_STRIDE + ap * 8) = pa0l;
        *(uint4*)(sA + ((p*2+0)*128 + a1r) * SA_STRIDE + ap * 8) = pa1h;
        *(uint4*)(sA + ((p*2+1)*128 + a1r) * SA_STRIDE + ap * 8) = pa1l;
        *(uint4*)(sB + ((p*2+0)*64  + a0r) * SA_STRIDE + ap * 8) = pbh;
        *(uint4*)(sB + ((p*2+1)*64  + a0r) * SA_STRIDE + ap * 8) = pbl;
        __syncthreads();

        if (st + 1 < 64) {
            const int kc = (st + 1) * 32;
            pa0h = *(const uint4*)(g_yhi + (size_t)(i0 + a0r) * (2 * HH) + kc + ap * 8);
            pa0l = *(const uint4*)(g_ylo + (size_t)(i0 + a0r) * (2 * HH) + kc + ap * 8);
            pa1h = *(const uint4*)(g_yhi + (size_t)(i0 + a1r) * (2 * HH) + kc + ap * 8);
            pa1l = *(const uint4*)(g_ylo + (size_t)(i0 + a1r) * (2 * HH) + kc + ap * 8);
            pbh  = *(const uint4*)(Bhi + (size_t)(j0 + a0r) * (2 * HH) + kc + ap * 8);
            pbl  = *(const uint4*)(Blo + (size_t)(j0 + a0r) * (2 * HH) + kc + ap * 8);
        }

#pragma unroll
        for (int kk = 0; kk < 32; kk += 16) {
            uint32_t ah[2][4], al[2][4];
#pragma unroll
            for (int mf = 0; mf < 2; ++mf) {
                const int r = mt * 32 + mf * 16 + gid;
                ah[mf][0] = *(const uint32_t*)(sA + ((p*2+0)*128 + r    ) * SA_STRIDE + kk + tg2);
                ah[mf][1] = *(const uint32_t*)(sA + ((p*2+0)*128 + r + 8) * SA_STRIDE + kk + tg2);
                ah[mf][2] = *(const uint32_t*)(sA + ((p*2+0)*128 + r    ) * SA_STRIDE + kk + tg2 + 8);
                ah[mf][3] = *(const uint32_t*)(sA + ((p*2+0)*128 + r + 8) * SA_STRIDE + kk + tg2 + 8);
                al[mf][0] = *(const uint32_t*)(sA + ((p*2+1)*128 + r    ) * SA_STRIDE + kk + tg2);
                al[mf][1] = *(const uint32_t*)(sA + ((p*2+1)*128 + r + 8) * SA_STRIDE + kk + tg2);
                al[mf][2] = *(const uint32_t*)(sA + ((p*2+1)*128 + r    ) * SA_STRIDE + kk + tg2 + 8);
                al[mf][3] = *(const uint32_t*)(sA + ((p*2+1)*128 + r + 8) * SA_STRIDE + kk + tg2 + 8);
            }
#pragma unroll
            for (int nf = 0; nf < 4; ++nf) {
                const int nr = nt * 32 + nf * 8 + gid;
                uint32_t bh0 = *(const uint32_t*)(sB + ((p*2+0)*64 + nr) * SA_STRIDE + kk + tg2);
                uint32_t bh1 = *(const uint32_t*)(sB + ((p*2+0)*64 + nr) * SA_STRIDE + kk + tg2 + 8);
                uint32_t bl0 = *(const uint32_t*)(sB + ((p*2+1)*64 + nr) * SA_STRIDE + kk + tg2);
                uint32_t bl1 = *(const uint32_t*)(sB + ((p*2+1)*64 + nr) * SA_STRIDE + kk + tg2 + 8);
                mma_bf16(acc[0][nf], ah[0][0], ah[0][1], ah[0][2], ah[0][3], bh0, bh1);
                mma_bf16(acc[1][nf], ah[1][0], ah[1][1], ah[1][2], ah[1][3], bh0, bh1);
                mma_bf16(acc[0][nf], al[0][0], al[0][1], al[0][2], al[0][3], bh0, bh1);
                mma_bf16(acc[1][nf], al[1][0], al[1][1], al[1][2], al[1][3], bh0, bh1);
                mma_bf16(acc[0][nf], ah[0][0], ah[0][1], ah[0][2], ah[0][3], bl0, bl1);
                mma_bf16(acc[1][nf], ah[1][0], ah[1][1], ah[1][2], ah[1][3], bl0, bl1);
            }
        }
        __syncthreads();
    }

#pragma unroll
    for (int mf = 0; mf < 2; ++mf) {
#pragma unroll
        for (int nf = 0; nf < 4; ++nf) {
            const int j  = j0 + nt * 32 + nf * 8 + tg2;
            const float bj0 = bih1[dir * G3 + j];
            const float bj1 = bih1[dir * G3 + j + 1];
            int i = i0 + mt * 32 + mf * 16 + gid;
            {
                const int b = i >> 8, t = i & 255;
                float2 v = make_float2(acc[mf][nf][0] + bj0, acc[mf][nf][1] + bj1);
                *(float2*)&g_xp1[(((size_t)dir * TT + t) * BB + b) * G3 + j] = v;
            }
            i += 8;
            {
                const int b = i >> 8, t = i & 255;
                float2 v = make_float2(acc[mf][nf][2] + bj0, acc[mf][nf][3] + bj1);
                *(float2*)&g_xp1[(((size_t)dir * TT + t) * BB + b) * G3 + j] = v;
            }
        }
    }
}

// ---------------------------------------------------------------------------
// Final hidden-state stack. hf0/hb0 reconstructed from split y0 (hi+lo).
// ---------------------------------------------------------------------------
__global__ void finalize_kernel(float* __restrict__ dout)
{
    const int idx = blockIdx.x * blockDim.x + threadIdx.x;
    const int l = idx >> 16;
    const int r = idx & 65535;
    const int b = r >> 10;
    const int h = r & 1023;
    float v;
    if (l == 0) {
        const size_t off = ((size_t)(b * TT + (TT - 1))) * (2 * HH) + h;
        v = __bfloat162float(g_yhi[off]) + __bfloat162float(g_ylo[off]);
    } else if (l == 1) {
        const size_t off = ((size_t)(b * TT + 0)) * (2 * HH) + HH + h;
        v = __bfloat162float(g_yhi[off]) + __bfloat162float(g_ylo[off]);
    } else if (l == 2) {
        v = dout[((size_t)b * TT + (TT - 1)) * (2 * HH) + h];
    } else {
        v = dout[((size_t)b * TT + 0) * (2 * HH) + HH + h];
    }
    dout[(size_t)BB * TT * 2 * HH + idx] = v;
}

// ---------------------------------------------------------------------------
extern "C" void kernel_launch(void* const* d_in, const int* in_sizes, int n_in,
                              void* d_out, int out_size)
{
    (void)in_sizes; (void)n_in; (void)out_size;
    const int*   x    = (const int*)  d_in[0];
    const float* Wih0 = (const float*)d_in[1];
    const float* Whh0 = (const float*)d_in[2];
    const float* bih0 = (const float*)d_in[3];
    const float* bhh0 = (const float*)d_in[4];
    const float* Wih1 = (const float*)d_in[5];
    const float* Whh1 = (const float*)d_in[6];
    const float* bih1 = (const float*)d_in[7];
    const float* bhh1 = (const float*)d_in[8];
    float* out = (float*)d_out;

    cudaFuncSetAttribute(xp1_mma_kernel,
                         cudaFuncAttributeMaxDynamicSharedMemorySize,
                         XSA_BYTES + XSB_BYTES);
    cudaFuncSetAttribute(gru_persist<0>,
                         cudaFuncAttributeMaxDynamicSharedMemorySize, SMEM_PERS);
    cudaFuncSetAttribute(gru_persist<1>,
                         cudaFuncAttributeMaxDynamicSharedMemorySize, SMEM_PERS);

    // Weight splits
    {
        const size_t nw = (size_t)2 * 2 * G3 * HH;
        split_whh_kernel<<<(unsigned)((nw + 255) / 256), 256>>>(Whh0, Whh1);
        const size_t ni = (size_t)2 * G3 * 2 * HH;
        split_wih1_kernel<<<(unsigned)((ni + 255) / 256), 256>>>(Wih1);
    }

    // Layer 0 recurrence (persistent, both dirs) -> writes split y into g_yhi/g_ylo
    reset_bar_kernel<<<1, 32>>>();
    gru_persist<0><<<dim3(64, 2), 384, SMEM_PERS>>>(bhh0, Wih0, bih0, x, out);

    // Layer-1 input projection (tensor cores), consumes g_yhi/g_ylo directly
    xp1_mma_kernel<<<dim3(48, 128, 2), 256, XSA_BYTES + XSB_BYTES>>>(bih1);

    // Layer 1 recurrence (persistent, both dirs) -> writes into d_out
    reset_bar_kernel<<<1, 32>>>();
    gru_persist<1><<<dim3(64, 2), 384, SMEM_PERS>>>(bhh1, (const float*)0, (const float*)0, x, out);

    // Hidden-state stack
    finalize_kernel<<<1024, 256>>>(out);
}

// round 16
// speedup vs baseline: 2.5124x; 1.0242x over previous
#include <cuda_runtime.h>
#include <cuda_bf16.h>
#include <math.h>
#include <stdint.h>

// Problem constants
#define BB   64      // batch
#define TT   256     // time
#define HH   1024    // hidden
#define G3   3072    // 3*H
#define VV   128     // vocab

// ---------------------------------------------------------------------------
// Device-global scratch (allocation-free workaround)
// ---------------------------------------------------------------------------
__device__ __align__(16) float g_xp1[(size_t)2 * TT * BB * G3]; // layer1 x-proj [dir][t][b][3H]
__device__ __align__(16) __nv_bfloat16 g_yhi[(size_t)BB * TT * 2 * HH]; // y0cat hi [b*256+t][2048]
__device__ __align__(16) __nv_bfloat16 g_ylo[(size_t)BB * TT * 2 * HH]; // y0cat lo
__device__ __align__(16) __nv_bfloat16 g_whi[(size_t)2 * G3 * 2 * HH];  // Wih1 hi
__device__ __align__(16) __nv_bfloat16 g_wlo[(size_t)2 * G3 * 2 * HH];  // Wih1 lo
__device__ __align__(16) __nv_bfloat16 g_whh_hi[(size_t)2 * 2 * G3 * HH]; // Whh hi [layer][dir][3072][1024]
__device__ __align__(16) __nv_bfloat16 g_whh_lo[(size_t)2 * 2 * G3 * HH]; // Whh lo
__device__ __align__(16) __nv_bfloat16 g_hhi[(size_t)2 * 2 * BB * HH];  // h hi [dir][parity][64][1024] (layer1)
__device__ __align__(16) __nv_bfloat16 g_hlo[(size_t)2 * 2 * BB * HH];  // h lo (layer1)
__device__ unsigned g_bar[2][32];                                        // per-dir barrier (padded)

// ---------------------------------------------------------------------------
// PTX helpers
// ---------------------------------------------------------------------------
__device__ __forceinline__ void mma_bf16(float d[4],
                                         uint32_t a0, uint32_t a1, uint32_t a2, uint32_t a3,
                                         uint32_t b0, uint32_t b1)
{
    asm volatile(
        "mma.sync.aligned.m16n8k16.row.col.f32.bf16.bf16.f32 "
        "{%0,%1,%2,%3}, {%4,%5,%6,%7}, {%8,%9}, {%0,%1,%2,%3};\n"
        : "+f"(d[0]), "+f"(d[1]), "+f"(d[2]), "+f"(d[3])
        : "r"(a0), "r"(a1), "r"(a2), "r"(a3), "r"(b0), "r"(b1));
}

__device__ __forceinline__ void ldsm_x4(uint32_t& r0, uint32_t& r1, uint32_t& r2, uint32_t& r3,
                                        uint32_t addr)
{
    asm volatile("ldmatrix.sync.aligned.m8n8.x4.shared.b16 {%0,%1,%2,%3}, [%4];"
                 : "=r"(r0), "=r"(r1), "=r"(r2), "=r"(r3) : "r"(addr));
}

__device__ __forceinline__ uint32_t smem_u32(const void* p) {
    uint32_t a;
    asm("{ .reg .u64 t; cvta.to.shared.u64 t, %1; cvt.u32.u64 %0, t; }" : "=r"(a) : "l"(p));
    return a;
}

__device__ __forceinline__ uint4 ldg_cg(const void* p) {
    uint4 v;
    asm volatile("ld.global.cg.v4.u32 {%0,%1,%2,%3}, [%4];"
                 : "=r"(v.x), "=r"(v.y), "=r"(v.z), "=r"(v.w) : "l"(p));
    return v;
}

__device__ __forceinline__ unsigned ldg_acq(const unsigned* p) {
    unsigned v;
    asm volatile("ld.global.acquire.gpu.u32 %0, [%1];" : "=r"(v) : "l"(p) : "memory");
    return v;
}

// ---------------------------------------------------------------------------
// Split kernels (fp32 -> hi/lo bf16)
// ---------------------------------------------------------------------------
__global__ void split_whh_kernel(const float* __restrict__ Whh0,
                                 const float* __restrict__ Whh1)
{
    const size_t idx = (size_t)blockIdx.x * 256 + threadIdx.x;
    const size_t per_layer = (size_t)2 * G3 * HH;
    if (idx >= 2 * per_layer) return;
    float w = (idx < per_layer) ? Whh0[idx] : Whh1[idx - per_layer];
    __nv_bfloat16 h = __float2bfloat16(w);
    g_whh_hi[idx] = h;
    g_whh_lo[idx] = __float2bfloat16(w - __bfloat162float(h));
}

__global__ void split_wih1_kernel(const float* __restrict__ Wih1)
{
    const size_t idx = (size_t)blockIdx.x * 256 + threadIdx.x;
    if (idx >= (size_t)2 * G3 * 2 * HH) return;
    float w = Wih1[idx];
    __nv_bfloat16 h = __float2bfloat16(w);
    g_whi[idx] = h;
    g_wlo[idx] = __float2bfloat16(w - __bfloat162float(h));
}

__global__ void reset_bar_kernel()
{
    if (threadIdx.x < 2) g_bar[threadIdx.x][0] = 0u;
    __threadfence();
}

// ---------------------------------------------------------------------------
// Persistent GRU layer kernel (all 256 steps in one launch).
// grid (64, 2): x = j-tile (16 cols), y = dir. 128 CTAs, 1 CTA/SM
// (smem-forced), single wave -> co-resident; per-dir grid barrier.
// Whh split weights resident in smem the whole kernel.
// block = 256 (8 warps): warp = (kh 0..1 split-K half) x (mt 0..3, m16).
// Each warp computes m16 x n48 (ALL 3 gates) over its k-half; k-halves are
// INTERLEAVED over chunks (kh == st&1) so both halves stream the same A
// buffer. A fragments: zero duplication (big smem-traffic cut vs R15).
// ---------------------------------------------------------------------------
#define SBW_PAD   1032
#define SBW_BYTES (2 * 48 * SBW_PAD * 2)      // 198144
#define SAP_BYTES (2 * 2 * 64 * 40 * 2)       // 20480
#define SMEM_PERS (SBW_BYTES + SAP_BYTES)     // 218624

template <int LAYER>
__global__ __launch_bounds__(256, 1)
void gru_persist(const float* __restrict__ bhh,    // [2][3072] (this layer)
                 const float* __restrict__ Wih0,   // [2][3072][128] (layer 0 only)
                 const float* __restrict__ bih0,   // [2][3072]      (layer 0 only)
                 const int*   __restrict__ xtok,   // [64][256]
                 float* __restrict__ dout)
{
    extern __shared__ __align__(16) char dsm[];
    __nv_bfloat16* sBw = (__nv_bfloat16*)dsm;               // [hl][48][1032]
    __nv_bfloat16* sA  = (__nv_bfloat16*)(dsm + SBW_BYTES); // [buf][hl][64][40]
    float*         sG  = (float*)(dsm + SBW_BYTES);         // alias sA: [3][64][20]
    float*         sR  = (float*)(dsm + SBW_BYTES);         // alias sA: [4][32][25]

    const int dir = blockIdx.y;
    const int j0  = blockIdx.x * 16;
    const int tid = threadIdx.x;
    const int wid = tid >> 5, lid = tid & 31;
    const int gid = lid >> 2, tg2 = (lid & 3) * 2;
    const int mt  = wid & 3;      // m-tile (batches mt*16..+15)
    const int kh  = wid >> 2;     // split-K half (0: even chunks, 1: odd)

    // ---- load persistent weight tile into smem (once) ----
    {
        const __nv_bfloat16* Bhi = g_whh_hi + ((size_t)(LAYER * 2 + dir)) * G3 * HH;
        const __nv_bfloat16* Blo = g_whh_lo + ((size_t)(LAYER * 2 + dir)) * G3 * HH;
        for (int e = tid; e < 48 * 8; e += 256) {
            const int r    = e >> 3;            // 0..47
            const int c0   = (e & 7) * 128;
            const int grow = (r >> 4) * HH + j0 + (r & 15);
#pragma unroll
            for (int u = 0; u < 128; u += 8) {
                *(uint4*)(sBw + (size_t)r * SBW_PAD + c0 + u) =
                    *(const uint4*)(Bhi + (size_t)grow * HH + c0 + u);
                *(uint4*)(sBw + (size_t)(48 + r) * SBW_PAD + c0 + u) =
                    *(const uint4*)(Blo + (size_t)grow * HH + c0 + u);
            }
        }
    }
    __syncthreads();

    // ---- ldmatrix per-lane base offsets ----
    const int lrow = ((lid >> 3) & 1) * 8 + (lid & 7);
    const int lcol = (lid >> 4) * 8;
    const uint32_t sA_u = smem_u32(sA);
    const uint32_t sB_u = smem_u32(sBw);
    const uint32_t aOff = (uint32_t)((mt * 16 + lrow) * 40 + lcol) * 2;
    uint32_t bHiOff[3], bLoOff[3];
#pragma unroll
    for (int g = 0; g < 3; ++g) {
        bHiOff[g] = sB_u + (uint32_t)((g * 16 + lrow) * SBW_PAD + lcol) * 2;
        bLoOff[g] = sB_u + (uint32_t)((48 + g * 16 + lrow) * SBW_PAD + lcol) * 2;
    }

    // ---- epilogue per-thread constants ----
    // cbr/cbz fold bih0 (additive inside sigmoid); cbn = bhh n-bias only
    // (multiplied by r); bih0's n-bias (cxn) added OUTSIDE r*().
    const int eb  = tid >> 2;          // batch 0..63
    const int jl0 = (tid & 3) * 4;
    float cbr[4], cbz[4], cbn[4], cxn[4];
#pragma unroll
    for (int u = 0; u < 4; ++u) {
        const int j = j0 + jl0 + u;
        float br = bhh[dir * G3 + j];
        float bz = bhh[dir * G3 + HH + j];
        float bn = bhh[dir * G3 + 2 * HH + j];
        float xn_b = 0.f;
        if (LAYER == 0) {
            br  += bih0[dir * G3 + j];
            bz  += bih0[dir * G3 + HH + j];
            xn_b = bih0[dir * G3 + 2 * HH + j];
        }
        cbr[u] = br; cbz[u] = bz; cbn[u] = bn; cxn[u] = xn_b;
    }

    // A staging roles (all 256 threads)
    const int arow = tid >> 2;         // batch row 0..63
    const int ap8  = (tid & 3) * 8;

    float hp[4] = {0.f, 0.f, 0.f, 0.f};

    for (int s = 0; s < TT; ++s) {
        const int t_x   = dir ? (TT - 1 - s) : s;
        const int tprev = dir ? (t_x + 1) : (t_x - 1);
        const int par   = s & 1;
        const int parN  = (s + 1) & 1;

        // ---- prefetch x-projection (step-invariant, overlaps barrier) ----
        float xr[4], xz[4], xn[4];
        if (LAYER == 0) {
            const int tok = xtok[eb * TT + t_x];
            const float* Wd = Wih0 + (size_t)dir * G3 * VV + tok;
#pragma unroll
            for (int u = 0; u < 4; ++u) {
                const int j = j0 + jl0 + u;
                xr[u] = Wd[(size_t)j * VV];
                xz[u] = Wd[(size_t)(HH + j) * VV];
                xn[u] = Wd[(size_t)(2 * HH + j) * VV] + cxn[u];
            }
        } else {
            const float* xp = g_xp1 + (((size_t)dir * TT + t_x) * BB + eb) * G3 + j0 + jl0;
            float4 v0 = *(const float4*)(xp);
            float4 v1 = *(const float4*)(xp + HH);
            float4 v2 = *(const float4*)(xp + 2 * HH);
            xr[0] = v0.x; xr[1] = v0.y; xr[2] = v0.z; xr[3] = v0.w;
            xz[0] = v1.x; xz[1] = v1.y; xz[2] = v1.z; xz[3] = v1.w;
            xn[0] = v2.x; xn[1] = v2.y; xn[2] = v2.z; xn[3] = v2.w;
        }

        float acc[3][2][4];   // [gate][nf][frag]
#pragma unroll
        for (int g = 0; g < 3; ++g)
#pragma unroll
            for (int nf = 0; nf < 2; ++nf)
#pragma unroll
                for (int q = 0; q < 4; ++q) acc[g][nf][q] = 0.f;

        if (s > 0) {
            // wait for all CTAs of this dir to finish step s-1 (acquire)
            if (tid == 0) {
                const unsigned target = 64u * (unsigned)s;
                while (ldg_acq(&g_bar[dir][0]) < target) __nanosleep(64);
            }
            __syncthreads();

            // per-thread A row base for this step
            const __nv_bfloat16* aHiBase;
            const __nv_bfloat16* aLoBase;
            if (LAYER == 0) {
                const size_t rowoff = ((size_t)(arow * TT + tprev)) * (2 * HH) + (size_t)dir * HH;
                aHiBase = g_yhi + rowoff;
                aLoBase = g_ylo + rowoff;
            } else {
                const size_t rowoff = ((size_t)(dir * 2 + par)) * BB * HH + (size_t)arow * HH;
                aHiBase = g_hhi + rowoff;
                aLoBase = g_hlo + rowoff;
            }

            // ---- mainloop: double-buffered, one sync per chunk,
            //      compute on chunks with st&1 == kh (interleaved split-K) ----
            {
                uint4 pah = ldg_cg(aHiBase + ap8);
                uint4 pal = ldg_cg(aLoBase + ap8);
                *(uint4*)(sA + (0 * 64 + arow) * 40 + ap8) = pah;
                *(uint4*)(sA + (1 * 64 + arow) * 40 + ap8) = pal;
            }
            __syncthreads();

            for (int st = 0; st < 32; ++st) {
                const int p = st & 1;
                uint4 nah, nal;
                if (st < 31) {
                    const int kc1 = (st + 1) * 32;
                    nah = ldg_cg(aHiBase + kc1 + ap8);
                    nal = ldg_cg(aLoBase + kc1 + ap8);
                }

                if ((st & 1) == kh) {
                    const int kc = st * 32;
                    const uint32_t aHi = sA_u + (uint32_t)(p * 2 + 0) * (64 * 40 * 2) + aOff;
                    const uint32_t aLo = sA_u + (uint32_t)(p * 2 + 1) * (64 * 40 * 2) + aOff;
#pragma unroll
                    for (int kk = 0; kk < 32; kk += 16) {
                        uint32_t ah0, ah1, ah2, ah3, al0, al1, al2, al3;
                        ldsm_x4(ah0, ah1, ah2, ah3, aHi + kk * 2);
                        ldsm_x4(al0, al1, al2, al3, aLo + kk * 2);
#pragma unroll
                        for (int g = 0; g < 3; ++g) {
                            uint32_t bh0, bh1, bh2, bh3, bl0, bl1, bl2, bl3;
                            ldsm_x4(bh0, bh1, bh2, bh3, bHiOff[g] + (kc + kk) * 2);
                            ldsm_x4(bl0, bl1, bl2, bl3, bLoOff[g] + (kc + kk) * 2);
                            mma_bf16(acc[g][0], ah0, ah1, ah2, ah3, bh0, bh2);
                            mma_bf16(acc[g][0], al0, al1, al2, al3, bh0, bh2);
                            mma_bf16(acc[g][0], ah0, ah1, ah2, ah3, bl0, bl2);
                            mma_bf16(acc[g][1], ah0, ah1, ah2, ah3, bh1, bh3);
                            mma_bf16(acc[g][1], al0, al1, al2, al3, bh1, bh3);
                            mma_bf16(acc[g][1], ah0, ah1, ah2, ah3, bl1, bl3);
                        }
                    }
                }

                if (st < 31) {
                    const int pn = p ^ 1;
                    *(uint4*)(sA + ((pn * 2 + 0) * 64 + arow) * 40 + ap8) = nah;
                    *(uint4*)(sA + ((pn * 2 + 1) * 64 + arow) * 40 + ap8) = nal;
                }
                __syncthreads();
            }

            // ---- split-K reduction (kh=1 -> smem -> kh=0 adds) ----
            if (kh == 1) {
                float* dst = sR + ((size_t)mt * 32 + lid) * 25;
#pragma unroll
                for (int g = 0; g < 3; ++g)
#pragma unroll
                    for (int nf = 0; nf < 2; ++nf)
#pragma unroll
                        for (int q = 0; q < 4; ++q)
                            dst[(g * 2 + nf) * 4 + q] = acc[g][nf][q];
            }
            __syncthreads();
            if (kh == 0) {
                const float* src = sR + ((size_t)mt * 32 + lid) * 25;
#pragma unroll
                for (int g = 0; g < 3; ++g)
#pragma unroll
                    for (int nf = 0; nf < 2; ++nf)
#pragma unroll
                        for (int q = 0; q < 4; ++q)
                            acc[g][nf][q] += src[(g * 2 + nf) * 4 + q];
            }
            __syncthreads();

            // ---- gate exchange (kh=0 warps hold full sums) ----
            if (kh == 0) {
                const int r0 = mt * 16 + gid;
#pragma unroll
                for (int g = 0; g < 3; ++g)
#pragma unroll
                    for (int nf = 0; nf < 2; ++nf) {
                        const int c0 = nf * 8 + tg2;
                        sG[(g * 64 + r0    ) * 20 + c0    ] = acc[g][nf][0];
                        sG[(g * 64 + r0    ) * 20 + c0 + 1] = acc[g][nf][1];
                        sG[(g * 64 + r0 + 8) * 20 + c0    ] = acc[g][nf][2];
                        sG[(g * 64 + r0 + 8) * 20 + c0 + 1] = acc[g][nf][3];
                    }
            }
            __syncthreads();
        }

        // ---------------- fused gate epilogue (all 256 threads) ----------------
        {
            float hn[4];
            __nv_bfloat16 hh[4], hl[4];
#pragma unroll
            for (int u = 0; u < 4; ++u) {
                const int jl = jl0 + u;
                float gr = 0.f, gz = 0.f, gn = 0.f;
                if (s > 0) {
                    gr = sG[(0 * 64 + eb) * 20 + jl];
                    gz = sG[(1 * 64 + eb) * 20 + jl];
                    gn = sG[(2 * 64 + eb) * 20 + jl];
                }
                float r = 1.f / (1.f + expf(-(xr[u] + gr + cbr[u])));
                float z = 1.f / (1.f + expf(-(xz[u] + gz + cbz[u])));
                float n = tanhf(xn[u] + r * (gn + cbn[u]));
                float h = (1.f - z) * n + z * hp[u];
                hn[u] = h; hp[u] = h;
                __nv_bfloat16 hb = __float2bfloat16(h);
                hh[u] = hb;
                hl[u] = __float2bfloat16(h - __bfloat162float(hb));
            }

            uint2 ph, pl;
            ph.x = ((uint32_t)__bfloat16_as_ushort(hh[1]) << 16) | __bfloat16_as_ushort(hh[0]);
            ph.y = ((uint32_t)__bfloat16_as_ushort(hh[3]) << 16) | __bfloat16_as_ushort(hh[2]);
            pl.x = ((uint32_t)__bfloat16_as_ushort(hl[1]) << 16) | __bfloat16_as_ushort(hl[0]);
            pl.y = ((uint32_t)__bfloat16_as_ushort(hl[3]) << 16) | __bfloat16_as_ushort(hl[2]);

            if (LAYER == 0) {
                // y doubles as h-state: split bf16 into g_yhi/g_ylo
                const size_t rowoff = ((size_t)(eb * TT + t_x)) * (2 * HH) + (size_t)dir * HH + j0 + jl0;
                *(uint2*)(g_yhi + rowoff) = ph;
                *(uint2*)(g_ylo + rowoff) = pl;
            } else {
                // fp32 y straight into d_out
                float* Y = dout + (dir ? HH : 0);
                *(float4*)&Y[(size_t)eb * (TT * 2 * HH) + (size_t)t_x * (2 * HH) + j0 + jl0] =
                    make_float4(hn[0], hn[1], hn[2], hn[3]);
                // split h state (parity) for next step
                const size_t rowoff = ((size_t)(dir * 2 + parN)) * BB * HH + (size_t)eb * HH + j0 + jl0;
                *(uint2*)(g_hhi + rowoff) = ph;
                *(uint2*)(g_hlo + rowoff) = pl;
            }
        }

        // publish: all writes visible, then arrive (release)
        __threadfence();
        __syncthreads();
        if (tid == 0) atomicAdd(&g_bar[dir][0], 1u);
    }
}

// ---------------------------------------------------------------------------
// Layer-1 input projection GEMM on tensor cores (bf16x3 split).
// CTA tile 128(i) x 64(j), KC=32, double-buffered; operands via ldmatrix.
// ---------------------------------------------------------------------------
#define SA_STRIDE 40
#define XSA_BYTES (2 * 2 * 128 * SA_STRIDE * 2)   // 40960
#define XSB_BYTES (2 * 2 * 64 * SA_STRIDE * 2)    // 20480

__global__ __launch_bounds__(256, 1)
void xp1_mma_kernel(const float* __restrict__ bih1)
{
    extern __shared__ __align__(16) char dsm[];
    __nv_bfloat16* sA = (__nv_bfloat16*)dsm;               // [buf][hl][128][40]
    __nv_bfloat16* sB = (__nv_bfloat16*)(dsm + XSA_BYTES); // [buf][hl][64][40]

    const int j0  = blockIdx.x * 64;
    const int i0  = blockIdx.y * 128;
    const int dir = blockIdx.z;
    const int tid = threadIdx.x;
    const int wid = tid >> 5;
    const int lid = tid & 31;
    const int gid = lid >> 2;
    const int tg2 = (lid & 3) * 2;
    const int mt  = wid >> 1;
    const int nt  = wid & 1;

    const __nv_bfloat16* Bhi = g_whi + (size_t)dir * G3 * (2 * HH);
    const __nv_bfloat16* Blo = g_wlo + (size_t)dir * G3 * (2 * HH);

    // ldmatrix per-lane offsets
    const int lrow = ((lid >> 3) & 1) * 8 + (lid & 7);
    const int lcol = (lid >> 4) * 8;
    const uint32_t sA_u = smem_u32(sA);
    const uint32_t sB_u = smem_u32(sB);

    float acc[2][4][4];
#pragma unroll
    for (int mf = 0; mf < 2; ++mf)
#pragma unroll
        for (int nf = 0; nf < 4; ++nf)
#pragma unroll
            for (int q = 0; q < 4; ++q) acc[mf][nf][q] = 0.f;

    const int a0r = tid >> 2, a1r = (tid + 256) >> 2;
    const int ap  = tid & 3;

    uint4 pa0h, pa0l, pa1h, pa1l, pbh, pbl;
    {
        pa0h = *(const uint4*)(g_yhi + (size_t)(i0 + a0r) * (2 * HH) + ap * 8);
        pa0l = *(const uint4*)(g_ylo + (size_t)(i0 + a0r) * (2 * HH) + ap * 8);
        pa1h = *(const uint4*)(g_yhi + (size_t)(i0 + a1r) * (2 * HH) + ap * 8);
        pa1l = *(const uint4*)(g_ylo + (size_t)(i0 + a1r) * (2 * HH) + ap * 8);
        pbh  = *(const uint4*)(Bhi + (size_t)(j0 + a0r) * (2 * HH) + ap * 8);
        pbl  = *(const uint4*)(Blo + (size_t)(j0 + a0r) * (2 * HH) + ap * 8);
    }

    for (int st = 0; st < 64; ++st) {
        const int p = st & 1;
        *(uint4*)(sA + ((p*2+0)*128 + a0r) * SA_STRIDE + ap * 8) = pa0h;
        *(uint4*)(sA + ((p*2+1)*128 + a0r) * SA_STRIDE + ap * 8) = pa0l;
        *(uint4*)(sA + ((p*2+0)*128 + a1r) * SA_STRIDE + ap * 8) = pa1h;
        *(uint4*)(sA + ((p*2+1)*128 + a1r) * SA_STRIDE + ap * 8) = pa1l;
        *(uint4*)(sB + ((p*2+0)*64  + a0r) * SA_STRIDE + ap * 8) = pbh;
        *(uint4*)(sB + ((p*2+1)*64  + a0r) * SA_STRIDE + ap * 8) = pbl;
        __syncthreads();

        if (st + 1 < 64) {
            const int kc = (st + 1) * 32;
            pa0h = *(const uint4*)(g_yhi + (size_t)(i0 + a0r) * (2 * HH) + kc + ap * 8);
            pa0l = *(const uint4*)(g_ylo + (size_t)(i0 + a0r) * (2 * HH) + kc + ap * 8);
            pa1h = *(const uint4*)(g_yhi + (size_t)(i0 + a1r) * (2 * HH) + kc + ap * 8);
            pa1l = *(const uint4*)(g_ylo + (size_t)(i0 + a1r) * (2 * HH) + kc + ap * 8);
            pbh  = *(const uint4*)(Bhi + (size_t)(j0 + a0r) * (2 * HH) + kc + ap * 8);
            pbl  = *(const uint4*)(Blo + (size_t)(j0 + a0r) * (2 * HH) + kc + ap * 8);
        }

#pragma unroll
        for (int kk = 0; kk < 32; kk += 16) {
            uint32_t fAh[2][4], fAl[2][4], fBh[2][4], fBl[2][4];
#pragma unroll
            for (int mf = 0; mf < 2; ++mf) {
                const uint32_t ra = (uint32_t)((mt * 32 + mf * 16 + lrow) * SA_STRIDE + kk + lcol) * 2;
                ldsm_x4(fAh[mf][0], fAh[mf][1], fAh[mf][2], fAh[mf][3],
                        sA_u + (uint32_t)(p * 2 + 0) * (128 * SA_STRIDE * 2) + ra);
                ldsm_x4(fAl[mf][0], fAl[mf][1], fAl[mf][2], fAl[mf][3],
                        sA_u + (uint32_t)(p * 2 + 1) * (128 * SA_STRIDE * 2) + ra);
            }
#pragma unroll
            for (int nb = 0; nb < 2; ++nb) {
                const uint32_t rb = (uint32_t)((nt * 32 + nb * 16 + lrow) * SA_STRIDE + kk + lcol) * 2;
                ldsm_x4(fBh[nb][0], fBh[nb][1], fBh[nb][2], fBh[nb][3],
                        sB_u + (uint32_t)(p * 2 + 0) * (64 * SA_STRIDE * 2) + rb);
                ldsm_x4(fBl[nb][0], fBl[nb][1], fBl[nb][2], fBl[nb][3],
                        sB_u + (uint32_t)(p * 2 + 1) * (64 * SA_STRIDE * 2) + rb);
            }
#pragma unroll
            for (int nf = 0; nf < 4; ++nf) {
                const int nb = nf >> 1, pp = nf & 1;
                const uint32_t b0h = fBh[nb][pp],     b1h = fBh[nb][pp + 2];
                const uint32_t b0l = fBl[nb][pp],     b1l = fBl[nb][pp + 2];
                mma_bf16(acc[0][nf], fAh[0][0], fAh[0][1], fAh[0][2], fAh[0][3], b0h, b1h);
                mma_bf16(acc[1][nf], fAh[1][0], fAh[1][1], fAh[1][2], fAh[1][3], b0h, b1h);
                mma_bf16(acc[0][nf], fAl[0][0], fAl[0][1], fAl[0][2], fAl[0][3], b0h, b1h);
                mma_bf16(acc[1][nf], fAl[1][0], fAl[1][1], fAl[1][2], fAl[1][3], b0h, b1h);
                mma_bf16(acc[0][nf], fAh[0][0], fAh[0][1], fAh[0][2], fAh[0][3], b0l, b1l);
                mma_bf16(acc[1][nf], fAh[1][0], fAh[1][1], fAh[1][2], fAh[1][3], b0l, b1l);
            }
        }
        __syncthreads();
    }

#pragma unroll
    for (int mf = 0; mf < 2; ++mf) {
#pragma unroll
        for (int nf = 0; nf < 4; ++nf) {
            const int j  = j0 + nt * 32 + nf * 8 + tg2;
            const float bj0 = bih1[dir * G3 + j];
            const float bj1 = bih1[dir * G3 + j + 1];
            int i = i0 + mt * 32 + mf * 16 + gid;
            {
                const int b = i >> 8, t = i & 255;
                float2 v = make_float2(acc[mf][nf][0] + bj0, acc[mf][nf][1] + bj1);
                *(float2*)&g_xp1[(((size_t)dir * TT + t) * BB + b) * G3 + j] = v;
            }
            i += 8;
            {
                const int b = i >> 8, t = i & 255;
                float2 v = make_float2(acc[mf][nf][2] + bj0, acc[mf][nf][3] + bj1);
                *(float2*)&g_xp1[(((size_t)dir * TT + t) * BB + b) * G3 + j] = v;
            }
        }
    }
}

// ---------------------------------------------------------------------------
// Final hidden-state stack. hf0/hb0 reconstructed from split y0 (hi+lo).
// ---------------------------------------------------------------------------
__global__ void finalize_kernel(float* __restrict__ dout)
{
    const int idx = blockIdx.x * blockDim.x + threadIdx.x;
    const int l = idx >> 16;
    const int r = idx & 65535;
    const int b = r >> 10;
    const int h = r & 1023;
    float v;
    if (l == 0) {
        const size_t off = ((size_t)(b * TT + (TT - 1))) * (2 * HH) + h;
        v = __bfloat162float(g_yhi[off]) + __bfloat162float(g_ylo[off]);
    } else if (l == 1) {
        const size_t off = ((size_t)(b * TT + 0)) * (2 * HH) + HH + h;
        v = __bfloat162float(g_yhi[off]) + __bfloat162float(g_ylo[off]);
    } else if (l == 2) {
        v = dout[((size_t)b * TT + (TT - 1)) * (2 * HH) + h];
    } else {
        v = dout[((size_t)b * TT + 0) * (2 * HH) + HH + h];
    }
    dout[(size_t)BB * TT * 2 * HH + idx] = v;
}

// ---------------------------------------------------------------------------
extern "C" void kernel_launch(void* const* d_in, const int* in_sizes, int n_in,
                              void* d_out, int out_size)
{
    (void)in_sizes; (void)n_in; (void)out_size;
    const int*   x    = (const int*)  d_in[0];
    const float* Wih0 = (const float*)d_in[1];
    const float* Whh0 = (const float*)d_in[2];
    const float* bih0 = (const float*)d_in[3];
    const float* bhh0 = (const float*)d_in[4];
    const float* Wih1 = (const float*)d_in[5];
    const float* Whh1 = (const float*)d_in[6];
    const float* bih1 = (const float*)d_in[7];
    const float* bhh1 = (const float*)d_in[8];
    float* out = (float*)d_out;

    cudaFuncSetAttribute(xp1_mma_kernel,
                         cudaFuncAttributeMaxDynamicSharedMemorySize,
                         XSA_BYTES + XSB_BYTES);
    cudaFuncSetAttribute(gru_persist<0>,
                         cudaFuncAttributeMaxDynamicSharedMemorySize, SMEM_PERS);
    cudaFuncSetAttribute(gru_persist<1>,
                         cudaFuncAttributeMaxDynamicSharedMemorySize, SMEM_PERS);

    // Weight splits
    {
        const size_t nw = (size_t)2 * 2 * G3 * HH;
        split_whh_kernel<<<(unsigned)((nw + 255) / 256), 256>>>(Whh0, Whh1);
        const size_t ni = (size_t)2 * G3 * 2 * HH;
        split_wih1_kernel<<<(unsigned)((ni + 255) / 256), 256>>>(Wih1);
    }

    // Layer 0 recurrence (persistent, both dirs) -> split y into g_yhi/g_ylo
    reset_bar_kernel<<<1, 32>>>();
    gru_persist<0><<<dim3(64, 2), 256, SMEM_PERS>>>(bhh0, Wih0, bih0, x, out);

    // Layer-1 input projection (tensor cores), consumes g_yhi/g_ylo directly
    xp1_mma_kernel<<<dim3(48, 128, 2), 256, XSA_BYTES + XSB_BYTES>>>(bih1);

    // Layer 1 recurrence (persistent, both dirs) -> writes into d_out
    reset_bar_kernel<<<1, 32>>>();
    gru_persist<1><<<dim3(64, 2), 256, SMEM_PERS>>>(bhh1, (const float*)0, (const float*)0, x, out);

    // Hidden-state stack
    finalize_kernel<<<1024, 256>>>(out);
}